// round 1
// baseline (speedup 1.0000x reference)
#include <cuda_runtime.h>
#include <math.h>

// Problem constants
#define BATCH 2
#define SEQ   2048
#define HID   1024
#define NH    16
#define HD    64
#define MROWS (BATCH * SEQ)   // 4096

// ---------------- scratch (static device globals; no runtime alloc) ----------
__device__ float g_q[MROWS * HID];
__device__ float g_k[MROWS * HID];
__device__ float g_v[MROWS * HID];
__device__ float g_att[MROWS * HID];

// ---------------- GEMM: out[M,N] = X[M,K] @ W[N,K]^T + bias[N] ---------------
// BM=BN=64, BK=16, 256 threads, 4x4 microtile per thread.
#define BM 64
#define BN 64
#define BK 16
#define GP 68   // padded smem stride (floats), 16B-aligned for float4

__global__ __launch_bounds__(256) void gemm_nt_bias(
    const float* __restrict__ X, const float* __restrict__ W,
    const float* __restrict__ bias, float* __restrict__ out,
    int M, int N, int K)
{
    __shared__ __align__(16) float As[BK][GP];  // As[k][m]
    __shared__ __align__(16) float Bs[BK][GP];  // Bs[k][n]

    const int t  = threadIdx.x;
    const int ty = t >> 4, tx = t & 15;
    const int r0 = ty << 2, c0 = tx << 2;
    const int m0 = blockIdx.y * BM;
    const int n0 = blockIdx.x * BN;

    float acc[4][4] = {};

    // loader mapping: 1024 elems per tile = 256 float4; one float4 per thread
    const int lm = t >> 2;          // row within tile (0..63)
    const int lk = (t & 3) << 2;    // k offset within tile (0,4,8,12)

    for (int k0 = 0; k0 < K; k0 += BK) {
        float4 xa = *(const float4*)&X[(size_t)(m0 + lm) * K + k0 + lk];
        float4 wb = *(const float4*)&W[(size_t)(n0 + lm) * K + k0 + lk];
        As[lk + 0][lm] = xa.x; As[lk + 1][lm] = xa.y;
        As[lk + 2][lm] = xa.z; As[lk + 3][lm] = xa.w;
        Bs[lk + 0][lm] = wb.x; Bs[lk + 1][lm] = wb.y;
        Bs[lk + 2][lm] = wb.z; Bs[lk + 3][lm] = wb.w;
        __syncthreads();

        #pragma unroll
        for (int kk = 0; kk < BK; ++kk) {
            float4 a = *(const float4*)&As[kk][r0];
            float4 b = *(const float4*)&Bs[kk][c0];
            const float av[4] = {a.x, a.y, a.z, a.w};
            const float bv[4] = {b.x, b.y, b.z, b.w};
            #pragma unroll
            for (int i = 0; i < 4; ++i)
                #pragma unroll
                for (int j = 0; j < 4; ++j)
                    acc[i][j] = fmaf(av[i], bv[j], acc[i][j]);
        }
        __syncthreads();
    }

    #pragma unroll
    for (int i = 0; i < 4; ++i) {
        #pragma unroll
        for (int j = 0; j < 4; ++j) {
            int n = n0 + c0 + j;
            out[(size_t)(m0 + r0 + i) * N + n] = acc[i][j] + bias[n];
        }
    }
}

// ---------------- Flash attention (fp32, online softmax) --------------------
// One CTA per (b, h, 64-query tile). 256 threads, 4x4 microtiles.
// smem layout (all stride GP=68, float4-aligned):
//   sQ: Qt[d][r]  (transposed)   sK: Kt[d][c] (transposed)
//   sV: V[k][d]   (natural)      sP: Pt[k][r] (transposed)
#define AQ 64   // query tile
#define AK 64   // key tile
#define TILE_F (AK * GP)               // floats per tile
#define ATT_SMEM_BYTES (4 * TILE_F * 4)

__global__ __launch_bounds__(256) void attn_kernel()
{
    extern __shared__ __align__(16) float smem[];
    float* sQ = smem;
    float* sK = smem + TILE_F;
    float* sV = smem + 2 * TILE_F;
    float* sP = smem + 3 * TILE_F;

    const int t  = threadIdx.x;
    const int ty = t >> 4, tx = t & 15;
    const int r0 = ty << 2, c0 = tx << 2;

    const int b  = blockIdx.z;
    const int h  = blockIdx.y;
    const int q0 = blockIdx.x * AQ;

    const float scale = 0.125f;  // HD^-0.5

    // loader mapping: 64 rows x 16 float4 = 1024 float4 / 256 thr = 4 each
    // iteration it: fid = t + it*256 -> row fid/16, dq = (fid%16)*4
    // Load Q tile transposed: Qt[d][r]
    #pragma unroll
    for (int it = 0; it < 4; ++it) {
        int fid = t + (it << 8);
        int r = fid >> 4;
        int dq = (fid & 15) << 2;
        float4 v = *(const float4*)&g_q[(size_t)(b * SEQ + q0 + r) * HID + h * HD + dq];
        sQ[(dq + 0) * GP + r] = v.x;
        sQ[(dq + 1) * GP + r] = v.y;
        sQ[(dq + 2) * GP + r] = v.z;
        sQ[(dq + 3) * GP + r] = v.w;
    }

    float O[4][4] = {};
    float mrow[4] = {-1e30f, -1e30f, -1e30f, -1e30f};
    float lrow[4] = {};

    __syncthreads();

    for (int k0 = 0; k0 < SEQ; k0 += AK) {
        // load K transposed and V natural
        #pragma unroll
        for (int it = 0; it < 4; ++it) {
            int fid = t + (it << 8);
            int r = fid >> 4;
            int dq = (fid & 15) << 2;
            size_t g = (size_t)(b * SEQ + k0 + r) * HID + h * HD + dq;
            float4 kv = *(const float4*)&g_k[g];
            sK[(dq + 0) * GP + r] = kv.x;
            sK[(dq + 1) * GP + r] = kv.y;
            sK[(dq + 2) * GP + r] = kv.z;
            sK[(dq + 3) * GP + r] = kv.w;
            float4 vv = *(const float4*)&g_v[g];
            *(float4*)&sV[r * GP + dq] = vv;
        }
        __syncthreads();

        // S = scale * Q K^T  for this thread's 4x4 patch
        float s[4][4] = {};
        #pragma unroll
        for (int d = 0; d < HD; ++d) {
            float4 qa = *(const float4*)&sQ[d * GP + r0];
            float4 kb = *(const float4*)&sK[d * GP + c0];
            const float av[4] = {qa.x, qa.y, qa.z, qa.w};
            const float bv[4] = {kb.x, kb.y, kb.z, kb.w};
            #pragma unroll
            for (int i = 0; i < 4; ++i)
                #pragma unroll
                for (int j = 0; j < 4; ++j)
                    s[i][j] = fmaf(av[i], bv[j], s[i][j]);
        }

        // online softmax update
        #pragma unroll
        for (int i = 0; i < 4; ++i) {
            float mt = fmaxf(fmaxf(s[i][0] * scale, s[i][1] * scale),
                             fmaxf(s[i][2] * scale, s[i][3] * scale));
            #pragma unroll
            for (int off = 8; off > 0; off >>= 1)
                mt = fmaxf(mt, __shfl_xor_sync(0xffffffffu, mt, off));
            float mnew = fmaxf(mrow[i], mt);
            float corr = __expf(mrow[i] - mnew);
            float rs = 0.f;
            #pragma unroll
            for (int j = 0; j < 4; ++j) {
                float p = __expf(s[i][j] * scale - mnew);
                s[i][j] = p;           // reuse s[][] as P patch
                rs += p;
            }
            #pragma unroll
            for (int off = 8; off > 0; off >>= 1)
                rs += __shfl_xor_sync(0xffffffffu, rs, off);
            lrow[i] = lrow[i] * corr + rs;
            mrow[i] = mnew;
            #pragma unroll
            for (int j = 0; j < 4; ++j)
                O[i][j] *= corr;
        }

        // stash P transposed: Pt[k][r]
        #pragma unroll
        for (int i = 0; i < 4; ++i)
            #pragma unroll
            for (int j = 0; j < 4; ++j)
                sP[(c0 + j) * GP + (r0 + i)] = s[i][j];
        __syncthreads();

        // O += P @ V
        #pragma unroll
        for (int k = 0; k < AK; ++k) {
            float4 pa = *(const float4*)&sP[k * GP + r0];
            float4 vb = *(const float4*)&sV[k * GP + c0];
            const float pv[4] = {pa.x, pa.y, pa.z, pa.w};
            const float vv[4] = {vb.x, vb.y, vb.z, vb.w};
            #pragma unroll
            for (int i = 0; i < 4; ++i)
                #pragma unroll
                for (int j = 0; j < 4; ++j)
                    O[i][j] = fmaf(pv[i], vv[j], O[i][j]);
        }
        __syncthreads();  // before K/V overwrite next iteration
    }

    // normalize + store to [B, L, D] with head offset
    #pragma unroll
    for (int i = 0; i < 4; ++i) {
        float inv = 1.f / lrow[i];
        #pragma unroll
        for (int j = 0; j < 4; ++j)
            g_att[(size_t)(b * SEQ + q0 + r0 + i) * HID + h * HD + c0 + j] = O[i][j] * inv;
    }
}

// ---------------- launch ----------------------------------------------------
extern "C" void kernel_launch(void* const* d_in, const int* in_sizes, int n_in,
                              void* d_out, int out_size)
{
    const float* hs = (const float*)d_in[0];
    const float* wq = (const float*)d_in[1];
    const float* bq = (const float*)d_in[2];
    const float* wk = (const float*)d_in[3];
    const float* bk = (const float*)d_in[4];
    const float* wv = (const float*)d_in[5];
    const float* bv = (const float*)d_in[6];
    const float* wo = (const float*)d_in[7];
    const float* bo = (const float*)d_in[8];
    float* out = (float*)d_out;

    float *qp, *kp, *vp, *ap;
    cudaGetSymbolAddress((void**)&qp, g_q);
    cudaGetSymbolAddress((void**)&kp, g_k);
    cudaGetSymbolAddress((void**)&vp, g_v);
    cudaGetSymbolAddress((void**)&ap, g_att);

    cudaFuncSetAttribute(attn_kernel, cudaFuncAttributeMaxDynamicSharedMemorySize,
                         ATT_SMEM_BYTES);

    dim3 ggrid(HID / BN, MROWS / BM);  // (16, 64)
    gemm_nt_bias<<<ggrid, 256>>>(hs, wq, bq, qp, MROWS, HID, HID);
    gemm_nt_bias<<<ggrid, 256>>>(hs, wk, bk, kp, MROWS, HID, HID);
    gemm_nt_bias<<<ggrid, 256>>>(hs, wv, bv, vp, MROWS, HID, HID);

    dim3 agrid(SEQ / AQ, NH, BATCH);   // (32, 16, 2)
    attn_kernel<<<agrid, 256, ATT_SMEM_BYTES>>>();

    gemm_nt_bias<<<ggrid, 256>>>(ap, wo, bo, out, MROWS, HID, HID);
}

// round 3
// speedup vs baseline: 1.6346x; 1.6346x over previous
#include <cuda_runtime.h>
#include <math.h>
#include <stdint.h>

// Problem constants
#define BATCH 2
#define SEQ   2048
#define HID   1024
#define NH    16
#define HD    64
#define MROWS (BATCH * SEQ)   // 4096

// ---------------- scratch (static device globals; no runtime alloc) ----------
__device__ float g_q[MROWS * HID];
__device__ float g_k[MROWS * HID];
__device__ float g_v[MROWS * HID];
__device__ float g_att[MROWS * HID];

// ============================================================================
// helpers
// ============================================================================
__device__ __forceinline__ void cp16(uint32_t s, const void* g) {
    asm volatile("cp.async.cg.shared.global [%0], [%1], 16;" :: "r"(s), "l"(g));
}
#define CP_COMMIT() asm volatile("cp.async.commit_group;" ::: "memory")
template <int N>
__device__ __forceinline__ void cp_wait() {
    asm volatile("cp.async.wait_group %0;" :: "n"(N) : "memory");
}
__device__ __forceinline__ uint32_t smem_u32(const void* p) {
    uint32_t a;
    asm("{ .reg .u64 t; cvta.to.shared.u64 t, %1; cvt.u32.u64 %0, t; }"
        : "=r"(a) : "l"(p));
    return a;
}
__device__ __forceinline__ uint32_t f2tf(float f) {
    uint32_t u;
    asm("cvt.rna.tf32.f32 %0, %1;" : "=r"(u) : "f"(f));
    return u;
}
__device__ __forceinline__ void mma_tf32(
    float& c0, float& c1, float& c2, float& c3,
    uint32_t a0, uint32_t a1, uint32_t a2, uint32_t a3,
    uint32_t b0, uint32_t b1)
{
    asm volatile(
        "mma.sync.aligned.m16n8k8.row.col.f32.tf32.tf32.f32 "
        "{%0,%1,%2,%3}, {%4,%5,%6,%7}, {%8,%9}, {%0,%1,%2,%3};"
        : "+f"(c0), "+f"(c1), "+f"(c2), "+f"(c3)
        : "r"(a0), "r"(a1), "r"(a2), "r"(a3), "r"(b0), "r"(b1));
}

// ============================================================================
// tf32 mma.sync GEMM: out[M,N] = X[M,K] @ W[N,K]^T + bias[N]
// CTA 128x128, 8 warps (warp tile 64x32), BK=32, double-buffered cp.async.
// smem rows padded to 36 floats (144B, 16B-aligned, conflict-free frags).
// ============================================================================
#define TBM 128
#define TBN 128
#define TBK 32
#define KSTAGES (HID / TBK)     // 32
#define ROWP 36                 // padded floats per 32-float row
#define MATF (128 * ROWP)       // floats per matrix per stage (4608)
#define MATB (MATF * 4)         // 18432 bytes
#define GEMM_SMEM (4 * MATB)    // 73728: [s0A][s0B][s1A][s1B]

__device__ __forceinline__ void g_load_stage(
    uint32_t sbase, int buf,
    const float* __restrict__ X, const float* __restrict__ W,
    int m0, int n0, int k0, int t)
{
    uint32_t aB = sbase + (uint32_t)(buf * 2) * MATB;
    uint32_t bB = aB + MATB;
    #pragma unroll
    for (int i = 0; i < 4; ++i) {
        int cid = t + (i << 8);          // 0..1023
        int r = cid >> 3;                // row 0..127
        int c = cid & 7;                 // 16B chunk 0..7
        uint32_t off = (uint32_t)r * 144 + (uint32_t)c * 16;
        cp16(aB + off, X + (size_t)(m0 + r) * HID + k0 + (c << 2));
        cp16(bB + off, W + (size_t)(n0 + r) * HID + k0 + (c << 2));
    }
}

__global__ __launch_bounds__(256, 2) void gemm_mma_tf32(
    const float* __restrict__ X, const float* __restrict__ W,
    const float* __restrict__ bias, float* __restrict__ out)
{
    extern __shared__ __align__(16) float smem[];
    const uint32_t sbase = smem_u32(smem);

    const int t    = threadIdx.x;
    const int wid  = t >> 5;
    const int lane = t & 31;
    const int wr   = (wid >> 2) << 6;   // warp row 0/64
    const int wc   = (wid & 3) << 5;    // warp col 0/32/64/96
    const int m0   = blockIdx.y * TBM;
    const int n0   = blockIdx.x * TBN;

    const int lr = lane >> 2;   // 0..7
    const int lc = lane & 3;    // 0..3

    float acc[4][4][4] = {};

    g_load_stage(sbase, 0, X, W, m0, n0, 0, t);
    CP_COMMIT();
    g_load_stage(sbase, 1, X, W, m0, n0, TBK, t);
    CP_COMMIT();

    for (int s = 0; s < KSTAGES; ++s) {
        const int buf = s & 1;
        cp_wait<1>();
        __syncthreads();

        const float* sA = smem + (size_t)(buf * 2) * MATF;
        const float* sB = sA + MATF;

        #pragma unroll
        for (int kk = 0; kk < 4; ++kk) {
            const int k = (kk << 3) + lc;
            uint32_t af[4][4];
            #pragma unroll
            for (int mi = 0; mi < 4; ++mi) {
                const int r = wr + (mi << 4) + lr;
                af[mi][0] = f2tf(sA[r * ROWP + k]);
                af[mi][1] = f2tf(sA[(r + 8) * ROWP + k]);
                af[mi][2] = f2tf(sA[r * ROWP + k + 4]);
                af[mi][3] = f2tf(sA[(r + 8) * ROWP + k + 4]);
            }
            uint32_t bf[4][2];
            #pragma unroll
            for (int ni = 0; ni < 4; ++ni) {
                const int n = wc + (ni << 3) + lr;
                bf[ni][0] = f2tf(sB[n * ROWP + k]);
                bf[ni][1] = f2tf(sB[n * ROWP + k + 4]);
            }
            #pragma unroll
            for (int mi = 0; mi < 4; ++mi)
                #pragma unroll
                for (int ni = 0; ni < 4; ++ni)
                    mma_tf32(acc[mi][ni][0], acc[mi][ni][1],
                             acc[mi][ni][2], acc[mi][ni][3],
                             af[mi][0], af[mi][1], af[mi][2], af[mi][3],
                             bf[ni][0], bf[ni][1]);
        }

        __syncthreads();
        if (s + 2 < KSTAGES) {
            g_load_stage(sbase, buf, X, W, m0, n0, (s + 2) * TBK, t);
            CP_COMMIT();
        }
    }

    // epilogue: C frag layout m16n8: c0,c1 -> (lr, 2*lc), c2,c3 -> (lr+8, 2*lc)
    #pragma unroll
    for (int mi = 0; mi < 4; ++mi) {
        #pragma unroll
        for (int ni = 0; ni < 4; ++ni) {
            const int row = m0 + wr + (mi << 4) + lr;
            const int col = n0 + wc + (ni << 3) + (lc << 1);
            float2 b01 = *(const float2*)&bias[col];
            float2 v0 = {acc[mi][ni][0] + b01.x, acc[mi][ni][1] + b01.y};
            float2 v1 = {acc[mi][ni][2] + b01.x, acc[mi][ni][3] + b01.y};
            *(float2*)&out[(size_t)row * HID + col] = v0;
            *(float2*)&out[(size_t)(row + 8) * HID + col] = v1;
        }
    }
}

// ---------------- Flash attention (fp32, online softmax) — unchanged --------
#define AQ 64
#define AK 64
#define GP 68
#define TILE_F (AK * GP)
#define ATT_SMEM_BYTES (4 * TILE_F * 4)

__global__ __launch_bounds__(256) void attn_kernel()
{
    extern __shared__ __align__(16) float asmem[];
    float* sQ = asmem;
    float* sK = asmem + TILE_F;
    float* sV = asmem + 2 * TILE_F;
    float* sP = asmem + 3 * TILE_F;

    const int t  = threadIdx.x;
    const int ty = t >> 4, tx = t & 15;
    const int r0 = ty << 2, c0 = tx << 2;

    const int b  = blockIdx.z;
    const int h  = blockIdx.y;
    const int q0 = blockIdx.x * AQ;

    const float scale = 0.125f;

    #pragma unroll
    for (int it = 0; it < 4; ++it) {
        int fid = t + (it << 8);
        int r = fid >> 4;
        int dq = (fid & 15) << 2;
        float4 v = *(const float4*)&g_q[(size_t)(b * SEQ + q0 + r) * HID + h * HD + dq];
        sQ[(dq + 0) * GP + r] = v.x;
        sQ[(dq + 1) * GP + r] = v.y;
        sQ[(dq + 2) * GP + r] = v.z;
        sQ[(dq + 3) * GP + r] = v.w;
    }

    float O[4][4] = {};
    float mrow[4] = {-1e30f, -1e30f, -1e30f, -1e30f};
    float lrow[4] = {};

    __syncthreads();

    for (int k0 = 0; k0 < SEQ; k0 += AK) {
        #pragma unroll
        for (int it = 0; it < 4; ++it) {
            int fid = t + (it << 8);
            int r = fid >> 4;
            int dq = (fid & 15) << 2;
            size_t g = (size_t)(b * SEQ + k0 + r) * HID + h * HD + dq;
            float4 kv = *(const float4*)&g_k[g];
            sK[(dq + 0) * GP + r] = kv.x;
            sK[(dq + 1) * GP + r] = kv.y;
            sK[(dq + 2) * GP + r] = kv.z;
            sK[(dq + 3) * GP + r] = kv.w;
            float4 vv = *(const float4*)&g_v[g];
            *(float4*)&sV[r * GP + dq] = vv;
        }
        __syncthreads();

        float s[4][4] = {};
        #pragma unroll
        for (int d = 0; d < HD; ++d) {
            float4 qa = *(const float4*)&sQ[d * GP + r0];
            float4 kb = *(const float4*)&sK[d * GP + c0];
            const float av[4] = {qa.x, qa.y, qa.z, qa.w};
            const float bv[4] = {kb.x, kb.y, kb.z, kb.w};
            #pragma unroll
            for (int i = 0; i < 4; ++i)
                #pragma unroll
                for (int j = 0; j < 4; ++j)
                    s[i][j] = fmaf(av[i], bv[j], s[i][j]);
        }

        #pragma unroll
        for (int i = 0; i < 4; ++i) {
            float mt = fmaxf(fmaxf(s[i][0] * scale, s[i][1] * scale),
                             fmaxf(s[i][2] * scale, s[i][3] * scale));
            #pragma unroll
            for (int off = 8; off > 0; off >>= 1)
                mt = fmaxf(mt, __shfl_xor_sync(0xffffffffu, mt, off));
            float mnew = fmaxf(mrow[i], mt);
            float corr = __expf(mrow[i] - mnew);
            float rs = 0.f;
            #pragma unroll
            for (int j = 0; j < 4; ++j) {
                float p = __expf(s[i][j] * scale - mnew);
                s[i][j] = p;
                rs += p;
            }
            #pragma unroll
            for (int off = 8; off > 0; off >>= 1)
                rs += __shfl_xor_sync(0xffffffffu, rs, off);
            lrow[i] = lrow[i] * corr + rs;
            mrow[i] = mnew;
            #pragma unroll
            for (int j = 0; j < 4; ++j)
                O[i][j] *= corr;
        }

        #pragma unroll
        for (int i = 0; i < 4; ++i)
            #pragma unroll
            for (int j = 0; j < 4; ++j)
                sP[(c0 + j) * GP + (r0 + i)] = s[i][j];
        __syncthreads();

        #pragma unroll
        for (int k = 0; k < AK; ++k) {
            float4 pa = *(const float4*)&sP[k * GP + r0];
            float4 vb = *(const float4*)&sV[k * GP + c0];
            const float pv[4] = {pa.x, pa.y, pa.z, pa.w};
            const float vv[4] = {vb.x, vb.y, vb.z, vb.w};
            #pragma unroll
            for (int i = 0; i < 4; ++i)
                #pragma unroll
                for (int j = 0; j < 4; ++j)
                    O[i][j] = fmaf(pv[i], vv[j], O[i][j]);
        }
        __syncthreads();
    }

    #pragma unroll
    for (int i = 0; i < 4; ++i) {
        float inv = 1.f / lrow[i];
        #pragma unroll
        for (int j = 0; j < 4; ++j)
            g_att[(size_t)(b * SEQ + q0 + r0 + i) * HID + h * HD + c0 + j] = O[i][j] * inv;
    }
}

// ---------------- launch ----------------------------------------------------
extern "C" void kernel_launch(void* const* d_in, const int* in_sizes, int n_in,
                              void* d_out, int out_size)
{
    const float* hs = (const float*)d_in[0];
    const float* wq = (const float*)d_in[1];
    const float* bq = (const float*)d_in[2];
    const float* wk = (const float*)d_in[3];
    const float* bk = (const float*)d_in[4];
    const float* wv = (const float*)d_in[5];
    const float* bv = (const float*)d_in[6];
    const float* wo = (const float*)d_in[7];
    const float* bo = (const float*)d_in[8];
    float* out = (float*)d_out;

    float *qp, *kp, *vp, *ap;
    cudaGetSymbolAddress((void**)&qp, g_q);
    cudaGetSymbolAddress((void**)&kp, g_k);
    cudaGetSymbolAddress((void**)&vp, g_v);
    cudaGetSymbolAddress((void**)&ap, g_att);

    cudaFuncSetAttribute(gemm_mma_tf32, cudaFuncAttributeMaxDynamicSharedMemorySize,
                         GEMM_SMEM);
    cudaFuncSetAttribute(attn_kernel, cudaFuncAttributeMaxDynamicSharedMemorySize,
                         ATT_SMEM_BYTES);

    dim3 ggrid(HID / TBN, MROWS / TBM);  // (8, 32)
    gemm_mma_tf32<<<ggrid, 256, GEMM_SMEM>>>(hs, wq, bq, qp);
    gemm_mma_tf32<<<ggrid, 256, GEMM_SMEM>>>(hs, wk, bk, kp);
    gemm_mma_tf32<<<ggrid, 256, GEMM_SMEM>>>(hs, wv, bv, vp);

    dim3 agrid(SEQ / AQ, NH, BATCH);     // (32, 16, 2)
    attn_kernel<<<agrid, 256, ATT_SMEM_BYTES>>>();

    gemm_mma_tf32<<<ggrid, 256, GEMM_SMEM>>>(ap, wo, bo, out);
}

// round 4
// speedup vs baseline: 3.2351x; 1.9792x over previous
#include <cuda_runtime.h>
#include <math.h>
#include <stdint.h>

// Problem constants
#define BATCH 2
#define SEQ   2048
#define HID   1024
#define NH    16
#define HD    64
#define MROWS (BATCH * SEQ)   // 4096

// ---------------- scratch (static device globals; no runtime alloc) ----------
__device__ float g_q[MROWS * HID];
__device__ float g_k[MROWS * HID];
__device__ float g_v[MROWS * HID];
__device__ float g_att[MROWS * HID];

// ============================================================================
// helpers
// ============================================================================
__device__ __forceinline__ void cp16(uint32_t s, const void* g) {
    asm volatile("cp.async.cg.shared.global [%0], [%1], 16;" :: "r"(s), "l"(g));
}
#define CP_COMMIT() asm volatile("cp.async.commit_group;" ::: "memory")
template <int N>
__device__ __forceinline__ void cp_wait() {
    asm volatile("cp.async.wait_group %0;" :: "n"(N) : "memory");
}
__device__ __forceinline__ uint32_t smem_u32(const void* p) {
    uint32_t a;
    asm("{ .reg .u64 t; cvta.to.shared.u64 t, %1; cvt.u32.u64 %0, t; }"
        : "=r"(a) : "l"(p));
    return a;
}
__device__ __forceinline__ uint32_t f2tf(float f) {
    uint32_t u;
    asm("cvt.rna.tf32.f32 %0, %1;" : "=r"(u) : "f"(f));
    return u;
}
__device__ __forceinline__ void mma_tf32(
    float& c0, float& c1, float& c2, float& c3,
    uint32_t a0, uint32_t a1, uint32_t a2, uint32_t a3,
    uint32_t b0, uint32_t b1)
{
    asm volatile(
        "mma.sync.aligned.m16n8k8.row.col.f32.tf32.tf32.f32 "
        "{%0,%1,%2,%3}, {%4,%5,%6,%7}, {%8,%9}, {%0,%1,%2,%3};"
        : "+f"(c0), "+f"(c1), "+f"(c2), "+f"(c3)
        : "r"(a0), "r"(a1), "r"(a2), "r"(a3), "r"(b0), "r"(b1));
}

// ============================================================================
// tf32 mma.sync GEMM: out[M,N] = X[M,K] @ W[N,K]^T + bias[N]   (as R3)
// ============================================================================
#define TBM 128
#define TBN 128
#define TBK 32
#define KSTAGES (HID / TBK)     // 32
#define ROWP 36
#define MATF (128 * ROWP)
#define MATB (MATF * 4)
#define GEMM_SMEM (4 * MATB)

__device__ __forceinline__ void g_load_stage(
    uint32_t sbase, int buf,
    const float* __restrict__ X, const float* __restrict__ W,
    int m0, int n0, int k0, int t)
{
    uint32_t aB = sbase + (uint32_t)(buf * 2) * MATB;
    uint32_t bB = aB + MATB;
    #pragma unroll
    for (int i = 0; i < 4; ++i) {
        int cid = t + (i << 8);
        int r = cid >> 3;
        int c = cid & 7;
        uint32_t off = (uint32_t)r * 144 + (uint32_t)c * 16;
        cp16(aB + off, X + (size_t)(m0 + r) * HID + k0 + (c << 2));
        cp16(bB + off, W + (size_t)(n0 + r) * HID + k0 + (c << 2));
    }
}

__global__ __launch_bounds__(256, 2) void gemm_mma_tf32(
    const float* __restrict__ X, const float* __restrict__ W,
    const float* __restrict__ bias, float* __restrict__ out)
{
    extern __shared__ __align__(16) float smem[];
    const uint32_t sbase = smem_u32(smem);

    const int t    = threadIdx.x;
    const int wid  = t >> 5;
    const int lane = t & 31;
    const int wr   = (wid >> 2) << 6;
    const int wc   = (wid & 3) << 5;
    const int m0   = blockIdx.y * TBM;
    const int n0   = blockIdx.x * TBN;

    const int lr = lane >> 2;
    const int lc = lane & 3;

    float acc[4][4][4] = {};

    g_load_stage(sbase, 0, X, W, m0, n0, 0, t);
    CP_COMMIT();
    g_load_stage(sbase, 1, X, W, m0, n0, TBK, t);
    CP_COMMIT();

    for (int s = 0; s < KSTAGES; ++s) {
        const int buf = s & 1;
        cp_wait<1>();
        __syncthreads();

        const float* sA = smem + (size_t)(buf * 2) * MATF;
        const float* sB = sA + MATF;

        #pragma unroll
        for (int kk = 0; kk < 4; ++kk) {
            const int k = (kk << 3) + lc;
            uint32_t af[4][4];
            #pragma unroll
            for (int mi = 0; mi < 4; ++mi) {
                const int r = wr + (mi << 4) + lr;
                af[mi][0] = f2tf(sA[r * ROWP + k]);
                af[mi][1] = f2tf(sA[(r + 8) * ROWP + k]);
                af[mi][2] = f2tf(sA[r * ROWP + k + 4]);
                af[mi][3] = f2tf(sA[(r + 8) * ROWP + k + 4]);
            }
            uint32_t bf[4][2];
            #pragma unroll
            for (int ni = 0; ni < 4; ++ni) {
                const int n = wc + (ni << 3) + lr;
                bf[ni][0] = f2tf(sB[n * ROWP + k]);
                bf[ni][1] = f2tf(sB[n * ROWP + k + 4]);
            }
            #pragma unroll
            for (int mi = 0; mi < 4; ++mi)
                #pragma unroll
                for (int ni = 0; ni < 4; ++ni)
                    mma_tf32(acc[mi][ni][0], acc[mi][ni][1],
                             acc[mi][ni][2], acc[mi][ni][3],
                             af[mi][0], af[mi][1], af[mi][2], af[mi][3],
                             bf[ni][0], bf[ni][1]);
        }

        __syncthreads();
        if (s + 2 < KSTAGES) {
            g_load_stage(sbase, buf, X, W, m0, n0, (s + 2) * TBK, t);
            CP_COMMIT();
        }
    }

    #pragma unroll
    for (int mi = 0; mi < 4; ++mi) {
        #pragma unroll
        for (int ni = 0; ni < 4; ++ni) {
            const int row = m0 + wr + (mi << 4) + lr;
            const int col = n0 + wc + (ni << 3) + (lc << 1);
            float2 b01 = *(const float2*)&bias[col];
            float2 v0 = {acc[mi][ni][0] + b01.x, acc[mi][ni][1] + b01.y};
            float2 v1 = {acc[mi][ni][2] + b01.x, acc[mi][ni][3] + b01.y};
            *(float2*)&out[(size_t)row * HID + col] = v0;
            *(float2*)&out[(size_t)(row + 8) * HID + col] = v1;
        }
    }
}

// ============================================================================
// Flash attention with mma.sync tf32
// CTA = (b, h, 128-q tile); 8 warps x 16 q-rows. K-tile = 64 keys, 2 stages.
// smem (floats): K[2][64*68] @0, V[2][64*72] @8704, P[8][16*68] @17920
// ============================================================================
#define QT   128
#define KT   64
#define NKT  (SEQ / KT)          // 32
#define KSP  68                  // K smem row stride (floats)
#define VSP  72                  // V smem row stride
#define PSP  68                  // P smem row stride
#define KSTG (KT * KSP)          // 4352 floats / stage
#define VSTG (KT * VSP)          // 4608
#define VBASE (2 * KSTG)         // 8704
#define PBASE (VBASE + 2 * VSTG) // 17920
#define PWARP (16 * PSP)         // 1088
#define ATT_SMEM_BYTES ((PBASE + 8 * PWARP) * 4)  // 106496

__device__ __forceinline__ void a_load_kv(
    uint32_t sbase, int buf, int b, int h, int k0, int t)
{
    const uint32_t kB = sbase + (uint32_t)buf * (KSTG * 4);
    const uint32_t vB = sbase + (uint32_t)(VBASE + buf * VSTG) * 4;
    #pragma unroll
    for (int i = 0; i < 4; ++i) {
        int cid = t + (i << 8);      // 0..1023
        int r = cid >> 4;            // key row 0..63
        int c = cid & 15;            // 16B chunk
        size_t g = (size_t)(b * SEQ + k0 + r) * HID + h * HD + (c << 2);
        cp16(kB + (uint32_t)r * (KSP * 4) + (uint32_t)c * 16, g_k + g);
        cp16(vB + (uint32_t)r * (VSP * 4) + (uint32_t)c * 16, g_v + g);
    }
}

__global__ __launch_bounds__(256) void attn_mma()
{
    extern __shared__ __align__(16) float smem[];
    const uint32_t sbase = smem_u32(smem);

    const int t    = threadIdx.x;
    const int wid  = t >> 5;
    const int lane = t & 31;
    const int lr   = lane >> 2;   // 0..7
    const int lc   = lane & 3;    // 0..3

    const int b  = blockIdx.z;
    const int h  = blockIdx.y;
    const int q0 = blockIdx.x * QT;
    const int wq = wid << 4;      // warp's q-row offset (16 rows)

    // ---- Q fragments: scaled, tf32, in registers for the whole kernel ----
    uint32_t qf[8][4];
    {
        const float* Qg = g_q + (size_t)(b * SEQ + q0 + wq) * HID + h * HD;
        #pragma unroll
        for (int ks = 0; ks < 8; ++ks) {
            const int col = (ks << 3) + lc;
            qf[ks][0] = f2tf(0.125f * Qg[(size_t)lr * HID + col]);
            qf[ks][1] = f2tf(0.125f * Qg[(size_t)(lr + 8) * HID + col]);
            qf[ks][2] = f2tf(0.125f * Qg[(size_t)lr * HID + col + 4]);
            qf[ks][3] = f2tf(0.125f * Qg[(size_t)(lr + 8) * HID + col + 4]);
        }
    }

    float O[8][4] = {};
    float mrow[2] = {-1e30f, -1e30f};
    float lrow[2] = {0.f, 0.f};

    a_load_kv(sbase, 0, b, h, 0, t);
    CP_COMMIT();
    a_load_kv(sbase, 1, b, h, KT, t);
    CP_COMMIT();

    float* sPw = smem + PBASE + wid * PWARP;

    for (int kt = 0; kt < NKT; ++kt) {
        const int buf = kt & 1;
        cp_wait<1>();
        __syncthreads();

        const float* sK = smem + buf * KSTG;
        const float* sV = smem + VBASE + buf * VSTG;

        // ---- S = Qs @ K^T  (16 x 64 per warp) ----
        float S[8][4] = {};
        #pragma unroll
        for (int ks = 0; ks < 8; ++ks) {
            const int k = (ks << 3) + lc;
            #pragma unroll
            for (int nt = 0; nt < 8; ++nt) {
                const int n = (nt << 3) + lr;
                uint32_t b0 = f2tf(sK[n * KSP + k]);
                uint32_t b1 = f2tf(sK[n * KSP + k + 4]);
                mma_tf32(S[nt][0], S[nt][1], S[nt][2], S[nt][3],
                         qf[ks][0], qf[ks][1], qf[ks][2], qf[ks][3], b0, b1);
            }
        }

        // ---- online softmax on fragments (rows lr and lr+8) ----
        #pragma unroll
        for (int r = 0; r < 2; ++r) {
            const int e0 = r << 1, e1 = e0 + 1;
            float mt = -1e30f;
            #pragma unroll
            for (int nt = 0; nt < 8; ++nt)
                mt = fmaxf(mt, fmaxf(S[nt][e0], S[nt][e1]));
            mt = fmaxf(mt, __shfl_xor_sync(0xffffffffu, mt, 1));
            mt = fmaxf(mt, __shfl_xor_sync(0xffffffffu, mt, 2));
            float mnew = fmaxf(mrow[r], mt);
            float corr = __expf(mrow[r] - mnew);
            float rs = 0.f;
            #pragma unroll
            for (int nt = 0; nt < 8; ++nt) {
                float p0 = __expf(S[nt][e0] - mnew);
                float p1 = __expf(S[nt][e1] - mnew);
                S[nt][e0] = p0; S[nt][e1] = p1;
                rs += p0 + p1;
            }
            rs += __shfl_xor_sync(0xffffffffu, rs, 1);
            rs += __shfl_xor_sync(0xffffffffu, rs, 2);
            lrow[r] = lrow[r] * corr + rs;
            mrow[r] = mnew;
            #pragma unroll
            for (int nt = 0; nt < 8; ++nt) {
                O[nt][e0] *= corr;
                O[nt][e1] *= corr;
            }
        }

        // ---- P -> per-warp smem (C-frag layout out, A-frag layout in) ----
        #pragma unroll
        for (int nt = 0; nt < 8; ++nt) {
            const int col = (nt << 3) + (lc << 1);
            *(float2*)&sPw[lr * PSP + col]       = make_float2(S[nt][0], S[nt][1]);
            *(float2*)&sPw[(lr + 8) * PSP + col] = make_float2(S[nt][2], S[nt][3]);
        }
        __syncwarp();

        // ---- O += P @ V ----
        #pragma unroll
        for (int ks = 0; ks < 8; ++ks) {
            const int k = (ks << 3) + lc;
            uint32_t a0 = f2tf(sPw[lr * PSP + k]);
            uint32_t a1 = f2tf(sPw[(lr + 8) * PSP + k]);
            uint32_t a2 = f2tf(sPw[lr * PSP + k + 4]);
            uint32_t a3 = f2tf(sPw[(lr + 8) * PSP + k + 4]);
            #pragma unroll
            for (int nt = 0; nt < 8; ++nt) {
                const int n = (nt << 3) + lr;
                uint32_t b0 = f2tf(sV[k * VSP + n]);
                uint32_t b1 = f2tf(sV[(k + 4) * VSP + n]);
                mma_tf32(O[nt][0], O[nt][1], O[nt][2], O[nt][3],
                         a0, a1, a2, a3, b0, b1);
            }
        }

        __syncthreads();  // K/V stage reuse
        if (kt + 2 < NKT) {
            a_load_kv(sbase, buf, b, h, (kt + 2) * KT, t);
            CP_COMMIT();
        }
    }

    // ---- normalize + store ----
    const float inv0 = 1.f / lrow[0];
    const float inv1 = 1.f / lrow[1];
    float* Og = g_att + (size_t)(b * SEQ + q0 + wq) * HID + h * HD;
    #pragma unroll
    for (int nt = 0; nt < 8; ++nt) {
        const int col = (nt << 3) + (lc << 1);
        *(float2*)&Og[(size_t)lr * HID + col] =
            make_float2(O[nt][0] * inv0, O[nt][1] * inv0);
        *(float2*)&Og[(size_t)(lr + 8) * HID + col] =
            make_float2(O[nt][2] * inv1, O[nt][3] * inv1);
    }
}

// ---------------- launch ----------------------------------------------------
extern "C" void kernel_launch(void* const* d_in, const int* in_sizes, int n_in,
                              void* d_out, int out_size)
{
    const float* hs = (const float*)d_in[0];
    const float* wq = (const float*)d_in[1];
    const float* bq = (const float*)d_in[2];
    const float* wk = (const float*)d_in[3];
    const float* bk = (const float*)d_in[4];
    const float* wv = (const float*)d_in[5];
    const float* bv = (const float*)d_in[6];
    const float* wo = (const float*)d_in[7];
    const float* bo = (const float*)d_in[8];
    float* out = (float*)d_out;

    float *qp, *kp, *vp, *ap;
    cudaGetSymbolAddress((void**)&qp, g_q);
    cudaGetSymbolAddress((void**)&kp, g_k);
    cudaGetSymbolAddress((void**)&vp, g_v);
    cudaGetSymbolAddress((void**)&ap, g_att);

    cudaFuncSetAttribute(gemm_mma_tf32, cudaFuncAttributeMaxDynamicSharedMemorySize,
                         GEMM_SMEM);
    cudaFuncSetAttribute(attn_mma, cudaFuncAttributeMaxDynamicSharedMemorySize,
                         ATT_SMEM_BYTES);

    dim3 ggrid(HID / TBN, MROWS / TBM);  // (8, 32)
    gemm_mma_tf32<<<ggrid, 256, GEMM_SMEM>>>(hs, wq, bq, qp);
    gemm_mma_tf32<<<ggrid, 256, GEMM_SMEM>>>(hs, wk, bk, kp);
    gemm_mma_tf32<<<ggrid, 256, GEMM_SMEM>>>(hs, wv, bv, vp);

    dim3 agrid(SEQ / QT, NH, BATCH);     // (16, 16, 2)
    attn_mma<<<agrid, 256, ATT_SMEM_BYTES>>>();

    gemm_mma_tf32<<<ggrid, 256, GEMM_SMEM>>>(ap, wo, bo, out);
}

// round 5
// speedup vs baseline: 3.8140x; 1.1789x over previous
#include <cuda_runtime.h>
#include <math.h>
#include <stdint.h>

// Problem constants
#define BATCH 2
#define SEQ   2048
#define HID   1024
#define NH    16
#define HD    64
#define MROWS (BATCH * SEQ)   // 4096

// ---------------- scratch (static device globals; no runtime alloc) ----------
__device__ float g_q[MROWS * HID];     // tf32 bits (pre-scaled by 0.125)
__device__ float g_k[MROWS * HID];     // tf32 bits
__device__ float g_v[MROWS * HID];     // tf32 bits
__device__ float g_att[MROWS * HID];   // tf32 bits
__device__ float g_hs[MROWS * HID];    // tf32 bits of hidden_states
__device__ float g_wq_t[HID * HID];
__device__ float g_wk_t[HID * HID];
__device__ float g_wv_t[HID * HID];
__device__ float g_wo_t[HID * HID];

// ============================================================================
// helpers
// ============================================================================
__device__ __forceinline__ void cp16(uint32_t s, const void* g) {
    asm volatile("cp.async.cg.shared.global [%0], [%1], 16;" :: "r"(s), "l"(g));
}
#define CP_COMMIT() asm volatile("cp.async.commit_group;" ::: "memory")
template <int N>
__device__ __forceinline__ void cp_wait() {
    asm volatile("cp.async.wait_group %0;" :: "n"(N) : "memory");
}
__device__ __forceinline__ uint32_t smem_u32(const void* p) {
    uint32_t a;
    asm("{ .reg .u64 t; cvta.to.shared.u64 t, %1; cvt.u32.u64 %0, t; }"
        : "=r"(a) : "l"(p));
    return a;
}
__device__ __forceinline__ uint32_t f2tf(float f) {
    uint32_t u;
    asm("cvt.rna.tf32.f32 %0, %1;" : "=r"(u) : "f"(f));
    return u;
}
__device__ __forceinline__ void mma_tf32(
    float& c0, float& c1, float& c2, float& c3,
    uint32_t a0, uint32_t a1, uint32_t a2, uint32_t a3,
    uint32_t b0, uint32_t b1)
{
    asm volatile(
        "mma.sync.aligned.m16n8k8.row.col.f32.tf32.tf32.f32 "
        "{%0,%1,%2,%3}, {%4,%5,%6,%7}, {%8,%9}, {%0,%1,%2,%3};"
        : "+f"(c0), "+f"(c1), "+f"(c2), "+f"(c3)
        : "r"(a0), "r"(a1), "r"(a2), "r"(a3), "r"(b0), "r"(b1));
}

// ============================================================================
// tf32 pre-convert kernel (one float4 per thread)
// ============================================================================
__global__ void conv_tf32(const float4* __restrict__ in, float4* __restrict__ out) {
    int i = blockIdx.x * blockDim.x + threadIdx.x;
    float4 v = in[i];
    float4 o;
    o.x = __uint_as_float(f2tf(v.x));
    o.y = __uint_as_float(f2tf(v.y));
    o.z = __uint_as_float(f2tf(v.z));
    o.w = __uint_as_float(f2tf(v.w));
    out[i] = o;
}

// ============================================================================
// tf32 mma.sync GEMM: out[M,N] = X[M,K] @ W[N,K]^T + bias[N]
// Inputs X, W already tf32-rounded. CVT_OUT: round output (after scale) to tf32.
// ============================================================================
#define TBM 128
#define TBN 128
#define TBK 32
#define KSTAGES (HID / TBK)     // 32
#define ROWP 36
#define MATF (128 * ROWP)
#define MATB (MATF * 4)
#define GEMM_SMEM (4 * MATB)

__device__ __forceinline__ void g_load_stage(
    uint32_t sbase, int buf,
    const float* __restrict__ X, const float* __restrict__ W,
    int m0, int n0, int k0, int t)
{
    uint32_t aB = sbase + (uint32_t)(buf * 2) * MATB;
    uint32_t bB = aB + MATB;
    #pragma unroll
    for (int i = 0; i < 4; ++i) {
        int cid = t + (i << 8);
        int r = cid >> 3;
        int c = cid & 7;
        uint32_t off = (uint32_t)r * 144 + (uint32_t)c * 16;
        cp16(aB + off, X + (size_t)(m0 + r) * HID + k0 + (c << 2));
        cp16(bB + off, W + (size_t)(n0 + r) * HID + k0 + (c << 2));
    }
}

template <bool CVT_OUT>
__global__ __launch_bounds__(256, 2) void gemm_mma_tf32(
    const float* __restrict__ X, const float* __restrict__ W,
    const float* __restrict__ bias, float* __restrict__ out, float oscale)
{
    extern __shared__ __align__(16) float smem[];
    const uint32_t sbase = smem_u32(smem);

    const int t    = threadIdx.x;
    const int wid  = t >> 5;
    const int lane = t & 31;
    const int wr   = (wid >> 2) << 6;
    const int wc   = (wid & 3) << 5;
    const int m0   = blockIdx.y * TBM;
    const int n0   = blockIdx.x * TBN;

    const int lr = lane >> 2;
    const int lc = lane & 3;

    float acc[4][4][4] = {};

    g_load_stage(sbase, 0, X, W, m0, n0, 0, t);
    CP_COMMIT();
    g_load_stage(sbase, 1, X, W, m0, n0, TBK, t);
    CP_COMMIT();

    for (int s = 0; s < KSTAGES; ++s) {
        const int buf = s & 1;
        cp_wait<1>();
        __syncthreads();

        const float* sA = smem + (size_t)(buf * 2) * MATF;
        const float* sB = sA + MATF;

        #pragma unroll
        for (int kk = 0; kk < 4; ++kk) {
            const int k = (kk << 3) + lc;
            uint32_t af[4][4];
            #pragma unroll
            for (int mi = 0; mi < 4; ++mi) {
                const int r = wr + (mi << 4) + lr;
                af[mi][0] = __float_as_uint(sA[r * ROWP + k]);
                af[mi][1] = __float_as_uint(sA[(r + 8) * ROWP + k]);
                af[mi][2] = __float_as_uint(sA[r * ROWP + k + 4]);
                af[mi][3] = __float_as_uint(sA[(r + 8) * ROWP + k + 4]);
            }
            uint32_t bf[4][2];
            #pragma unroll
            for (int ni = 0; ni < 4; ++ni) {
                const int n = wc + (ni << 3) + lr;
                bf[ni][0] = __float_as_uint(sB[n * ROWP + k]);
                bf[ni][1] = __float_as_uint(sB[n * ROWP + k + 4]);
            }
            #pragma unroll
            for (int mi = 0; mi < 4; ++mi)
                #pragma unroll
                for (int ni = 0; ni < 4; ++ni)
                    mma_tf32(acc[mi][ni][0], acc[mi][ni][1],
                             acc[mi][ni][2], acc[mi][ni][3],
                             af[mi][0], af[mi][1], af[mi][2], af[mi][3],
                             bf[ni][0], bf[ni][1]);
        }

        __syncthreads();
        if (s + 2 < KSTAGES) {
            g_load_stage(sbase, buf, X, W, m0, n0, (s + 2) * TBK, t);
            CP_COMMIT();
        }
    }

    #pragma unroll
    for (int mi = 0; mi < 4; ++mi) {
        #pragma unroll
        for (int ni = 0; ni < 4; ++ni) {
            const int row = m0 + wr + (mi << 4) + lr;
            const int col = n0 + wc + (ni << 3) + (lc << 1);
            float2 b01 = *(const float2*)&bias[col];
            float2 v0, v1;
            if (CVT_OUT) {
                v0.x = __uint_as_float(f2tf(oscale * (acc[mi][ni][0] + b01.x)));
                v0.y = __uint_as_float(f2tf(oscale * (acc[mi][ni][1] + b01.y)));
                v1.x = __uint_as_float(f2tf(oscale * (acc[mi][ni][2] + b01.x)));
                v1.y = __uint_as_float(f2tf(oscale * (acc[mi][ni][3] + b01.y)));
            } else {
                v0 = make_float2(acc[mi][ni][0] + b01.x, acc[mi][ni][1] + b01.y);
                v1 = make_float2(acc[mi][ni][2] + b01.x, acc[mi][ni][3] + b01.y);
            }
            *(float2*)&out[(size_t)row * HID + col] = v0;
            *(float2*)&out[(size_t)(row + 8) * HID + col] = v1;
        }
    }
}

// ============================================================================
// Flash attention with mma.sync tf32. Inputs g_q/g_k/g_v already tf32 bits,
// Q pre-scaled by 0.125. CTA = (b, h, 64-q tile); 4 warps x 16 q-rows.
// K-tile = 64 keys, double buffered. 128 threads, 2 CTAs/SM.
// ============================================================================
#define QT   64
#define ATTW 4                   // warps
#define ATHR 128
#define KT   64
#define NKT  (SEQ / KT)          // 32
#define KSP  68
#define VSP  72
#define PSP  68
#define KSTG (KT * KSP)          // 4352
#define VSTG (KT * VSP)          // 4608
#define VBASE (2 * KSTG)         // 8704
#define PBASE (VBASE + 2 * VSTG) // 17920
#define PWARP (16 * PSP)         // 1088
#define ATT_SMEM_BYTES ((PBASE + ATTW * PWARP) * 4)  // 89088

__device__ __forceinline__ void a_load_kv(
    uint32_t sbase, int buf, int b, int h, int k0, int t)
{
    const uint32_t kB = sbase + (uint32_t)buf * (KSTG * 4);
    const uint32_t vB = sbase + (uint32_t)(VBASE + buf * VSTG) * 4;
    #pragma unroll
    for (int i = 0; i < 8; ++i) {
        int cid = t + (i << 7);      // 0..1023
        int r = cid >> 4;            // key row 0..63
        int c = cid & 15;            // 16B chunk
        size_t g = (size_t)(b * SEQ + k0 + r) * HID + h * HD + (c << 2);
        cp16(kB + (uint32_t)r * (KSP * 4) + (uint32_t)c * 16, g_k + g);
        cp16(vB + (uint32_t)r * (VSP * 4) + (uint32_t)c * 16, g_v + g);
    }
}

__global__ __launch_bounds__(ATHR, 2) void attn_mma()
{
    extern __shared__ __align__(16) float smem[];
    const uint32_t sbase = smem_u32(smem);

    const int t    = threadIdx.x;
    const int wid  = t >> 5;
    const int lane = t & 31;
    const int lr   = lane >> 2;   // 0..7
    const int lc   = lane & 3;    // 0..3

    const int b  = blockIdx.z;
    const int h  = blockIdx.y;
    const int q0 = blockIdx.x * QT;
    const int wq = wid << 4;

    // Q fragments: raw tf32 bits (pre-scaled in projection epilogue)
    uint32_t qf[8][4];
    {
        const float* Qg = g_q + (size_t)(b * SEQ + q0 + wq) * HID + h * HD;
        #pragma unroll
        for (int ks = 0; ks < 8; ++ks) {
            const int col = (ks << 3) + lc;
            qf[ks][0] = __float_as_uint(Qg[(size_t)lr * HID + col]);
            qf[ks][1] = __float_as_uint(Qg[(size_t)(lr + 8) * HID + col]);
            qf[ks][2] = __float_as_uint(Qg[(size_t)lr * HID + col + 4]);
            qf[ks][3] = __float_as_uint(Qg[(size_t)(lr + 8) * HID + col + 4]);
        }
    }

    float O[8][4] = {};
    float mrow[2] = {-1e30f, -1e30f};
    float lrow[2] = {0.f, 0.f};

    a_load_kv(sbase, 0, b, h, 0, t);
    CP_COMMIT();
    a_load_kv(sbase, 1, b, h, KT, t);
    CP_COMMIT();

    float* sPw = smem + PBASE + wid * PWARP;

    for (int kt = 0; kt < NKT; ++kt) {
        const int buf = kt & 1;
        cp_wait<1>();
        __syncthreads();

        const float* sK = smem + buf * KSTG;
        const float* sV = smem + VBASE + buf * VSTG;

        // ---- S = Qs @ K^T ----
        float S[8][4] = {};
        #pragma unroll
        for (int ks = 0; ks < 8; ++ks) {
            const int k = (ks << 3) + lc;
            #pragma unroll
            for (int nt = 0; nt < 8; ++nt) {
                const int n = (nt << 3) + lr;
                uint32_t b0 = __float_as_uint(sK[n * KSP + k]);
                uint32_t b1 = __float_as_uint(sK[n * KSP + k + 4]);
                mma_tf32(S[nt][0], S[nt][1], S[nt][2], S[nt][3],
                         qf[ks][0], qf[ks][1], qf[ks][2], qf[ks][3], b0, b1);
            }
        }

        // ---- online softmax on fragments ----
        #pragma unroll
        for (int r = 0; r < 2; ++r) {
            const int e0 = r << 1, e1 = e0 + 1;
            float mt = -1e30f;
            #pragma unroll
            for (int nt = 0; nt < 8; ++nt)
                mt = fmaxf(mt, fmaxf(S[nt][e0], S[nt][e1]));
            mt = fmaxf(mt, __shfl_xor_sync(0xffffffffu, mt, 1));
            mt = fmaxf(mt, __shfl_xor_sync(0xffffffffu, mt, 2));
            float mnew = fmaxf(mrow[r], mt);
            float corr = __expf(mrow[r] - mnew);
            float rs = 0.f;
            #pragma unroll
            for (int nt = 0; nt < 8; ++nt) {
                float p0 = __expf(S[nt][e0] - mnew);
                float p1 = __expf(S[nt][e1] - mnew);
                S[nt][e0] = p0; S[nt][e1] = p1;
                rs += p0 + p1;
            }
            rs += __shfl_xor_sync(0xffffffffu, rs, 1);
            rs += __shfl_xor_sync(0xffffffffu, rs, 2);
            lrow[r] = lrow[r] * corr + rs;
            mrow[r] = mnew;
            #pragma unroll
            for (int nt = 0; nt < 8; ++nt) {
                O[nt][e0] *= corr;
                O[nt][e1] *= corr;
            }
        }

        // ---- P -> per-warp smem as tf32 bits ----
        #pragma unroll
        for (int nt = 0; nt < 8; ++nt) {
            const int col = (nt << 3) + (lc << 1);
            float2 p0 = make_float2(__uint_as_float(f2tf(S[nt][0])),
                                    __uint_as_float(f2tf(S[nt][1])));
            float2 p1 = make_float2(__uint_as_float(f2tf(S[nt][2])),
                                    __uint_as_float(f2tf(S[nt][3])));
            *(float2*)&sPw[lr * PSP + col]       = p0;
            *(float2*)&sPw[(lr + 8) * PSP + col] = p1;
        }
        __syncwarp();

        // ---- O += P @ V ----
        #pragma unroll
        for (int ks = 0; ks < 8; ++ks) {
            const int k = (ks << 3) + lc;
            uint32_t a0 = __float_as_uint(sPw[lr * PSP + k]);
            uint32_t a1 = __float_as_uint(sPw[(lr + 8) * PSP + k]);
            uint32_t a2 = __float_as_uint(sPw[lr * PSP + k + 4]);
            uint32_t a3 = __float_as_uint(sPw[(lr + 8) * PSP + k + 4]);
            #pragma unroll
            for (int nt = 0; nt < 8; ++nt) {
                const int n = (nt << 3) + lr;
                uint32_t b0 = __float_as_uint(sV[k * VSP + n]);
                uint32_t b1 = __float_as_uint(sV[(k + 4) * VSP + n]);
                mma_tf32(O[nt][0], O[nt][1], O[nt][2], O[nt][3],
                         a0, a1, a2, a3, b0, b1);
            }
        }

        __syncthreads();
        if (kt + 2 < NKT) {
            a_load_kv(sbase, buf, b, h, (kt + 2) * KT, t);
            CP_COMMIT();
        }
    }

    // ---- normalize + store as tf32 bits (input to O-projection) ----
    const float inv0 = 1.f / lrow[0];
    const float inv1 = 1.f / lrow[1];
    float* Og = g_att + (size_t)(b * SEQ + q0 + wq) * HID + h * HD;
    #pragma unroll
    for (int nt = 0; nt < 8; ++nt) {
        const int col = (nt << 3) + (lc << 1);
        float2 v0 = make_float2(__uint_as_float(f2tf(O[nt][0] * inv0)),
                                __uint_as_float(f2tf(O[nt][1] * inv0)));
        float2 v1 = make_float2(__uint_as_float(f2tf(O[nt][2] * inv1)),
                                __uint_as_float(f2tf(O[nt][3] * inv1)));
        *(float2*)&Og[(size_t)lr * HID + col] = v0;
        *(float2*)&Og[(size_t)(lr + 8) * HID + col] = v1;
    }
}

// ---------------- launch ----------------------------------------------------
extern "C" void kernel_launch(void* const* d_in, const int* in_sizes, int n_in,
                              void* d_out, int out_size)
{
    const float* hs = (const float*)d_in[0];
    const float* wq = (const float*)d_in[1];
    const float* bq = (const float*)d_in[2];
    const float* wk = (const float*)d_in[3];
    const float* bk = (const float*)d_in[4];
    const float* wv = (const float*)d_in[5];
    const float* bv = (const float*)d_in[6];
    const float* wo = (const float*)d_in[7];
    const float* bo = (const float*)d_in[8];
    float* out = (float*)d_out;

    float *qp, *kp, *vp, *ap, *hp, *wqp, *wkp, *wvp, *wop;
    cudaGetSymbolAddress((void**)&qp, g_q);
    cudaGetSymbolAddress((void**)&kp, g_k);
    cudaGetSymbolAddress((void**)&vp, g_v);
    cudaGetSymbolAddress((void**)&ap, g_att);
    cudaGetSymbolAddress((void**)&hp, g_hs);
    cudaGetSymbolAddress((void**)&wqp, g_wq_t);
    cudaGetSymbolAddress((void**)&wkp, g_wk_t);
    cudaGetSymbolAddress((void**)&wvp, g_wv_t);
    cudaGetSymbolAddress((void**)&wop, g_wo_t);

    cudaFuncSetAttribute(gemm_mma_tf32<true>,
                         cudaFuncAttributeMaxDynamicSharedMemorySize, GEMM_SMEM);
    cudaFuncSetAttribute(gemm_mma_tf32<false>,
                         cudaFuncAttributeMaxDynamicSharedMemorySize, GEMM_SMEM);
    cudaFuncSetAttribute(attn_mma,
                         cudaFuncAttributeMaxDynamicSharedMemorySize, ATT_SMEM_BYTES);

    // pre-convert inputs to tf32
    conv_tf32<<<(MROWS * HID / 4) / 256, 256>>>((const float4*)hs, (float4*)hp);
    conv_tf32<<<(HID * HID / 4) / 256, 256>>>((const float4*)wq, (float4*)wqp);
    conv_tf32<<<(HID * HID / 4) / 256, 256>>>((const float4*)wk, (float4*)wkp);
    conv_tf32<<<(HID * HID / 4) / 256, 256>>>((const float4*)wv, (float4*)wvp);
    conv_tf32<<<(HID * HID / 4) / 256, 256>>>((const float4*)wo, (float4*)wop);

    dim3 ggrid(HID / TBN, MROWS / TBM);  // (8, 32)
    gemm_mma_tf32<true><<<ggrid, 256, GEMM_SMEM>>>(hp, wqp, bq, qp, 0.125f);
    gemm_mma_tf32<true><<<ggrid, 256, GEMM_SMEM>>>(hp, wkp, bk, kp, 1.0f);
    gemm_mma_tf32<true><<<ggrid, 256, GEMM_SMEM>>>(hp, wvp, bv, vp, 1.0f);

    dim3 agrid(SEQ / QT, NH, BATCH);     // (32, 16, 2)
    attn_mma<<<agrid, ATHR, ATT_SMEM_BYTES>>>();

    gemm_mma_tf32<false><<<ggrid, 256, GEMM_SMEM>>>(ap, wop, bo, out, 1.0f);
}

// round 6
// speedup vs baseline: 6.4708x; 1.6966x over previous
#include <cuda_runtime.h>
#include <cuda_fp16.h>
#include <math.h>
#include <stdint.h>

// Problem constants
#define BATCH 2
#define SEQ   2048
#define HID   1024
#define NH    16
#define HD    64
#define MROWS (BATCH * SEQ)   // 4096

// ---------------- scratch (static device globals; no runtime alloc) ----------
__device__ __half g_q[MROWS * HID];    // half, pre-scaled by 0.125
__device__ __half g_k[MROWS * HID];    // half, [seq][hid]
__device__ __half g_vt[MROWS * HID];   // half, transposed: [(b*NH+h)*HD+d][seq]
__device__ __half g_att[MROWS * HID];  // half, [seq][hid]
__device__ __half g_hs[MROWS * HID];   // half of hidden_states
__device__ __half g_wq[HID * HID];
__device__ __half g_wk[HID * HID];
__device__ __half g_wv[HID * HID];
__device__ __half g_wo[HID * HID];

// ============================================================================
// helpers
// ============================================================================
__device__ __forceinline__ void cp16(uint32_t s, const void* g) {
    asm volatile("cp.async.cg.shared.global [%0], [%1], 16;" :: "r"(s), "l"(g));
}
#define CP_COMMIT() asm volatile("cp.async.commit_group;" ::: "memory")
template <int N>
__device__ __forceinline__ void cp_wait() {
    asm volatile("cp.async.wait_group %0;" :: "n"(N) : "memory");
}
__device__ __forceinline__ uint32_t smem_u32(const void* p) {
    uint32_t a;
    asm("{ .reg .u64 t; cvta.to.shared.u64 t, %1; cvt.u32.u64 %0, t; }"
        : "=r"(a) : "l"(p));
    return a;
}
__device__ __forceinline__ void mma_f16(
    float& c0, float& c1, float& c2, float& c3,
    uint32_t a0, uint32_t a1, uint32_t a2, uint32_t a3,
    uint32_t b0, uint32_t b1)
{
    asm volatile(
        "mma.sync.aligned.m16n8k16.row.col.f32.f16.f16.f32 "
        "{%0,%1,%2,%3}, {%4,%5,%6,%7}, {%8,%9}, {%0,%1,%2,%3};"
        : "+f"(c0), "+f"(c1), "+f"(c2), "+f"(c3)
        : "r"(a0), "r"(a1), "r"(a2), "r"(a3), "r"(b0), "r"(b1));
}
__device__ __forceinline__ uint32_t pack_h2(float a, float b) {
    __half2 h = __floats2half2_rn(a, b);
    return *(uint32_t*)&h;
}

// ============================================================================
// f32 -> half convert (one float4 -> two half2 per thread)
// ============================================================================
__global__ void conv_h(const float4* __restrict__ in, __half2* __restrict__ out) {
    int i = blockIdx.x * blockDim.x + threadIdx.x;
    float4 v = in[i];
    out[2 * i]     = __floats2half2_rn(v.x, v.y);
    out[2 * i + 1] = __floats2half2_rn(v.z, v.w);
}

// ============================================================================
// fp16 mma.sync GEMM: acc[M,N] = X[M,K] @ W[N,K]^T  (fp32 accum)
// CTA 128x128, 8 warps (64x32 warp tile), BK=32, double-buffered cp.async.
// MODE 0: out f32 = acc + bias
// MODE 1: out half = oscale*(acc + bias), natural [m][n]
// MODE 2: out half = acc + bias, transposed to g_vt [(b*NH+h)*HD+d][seq]
// ============================================================================
#define TBM 128
#define TBN 128
#define TBK 32
#define KSTAGES (HID / TBK)     // 32
#define ASTR 40                 // halfs per smem row (80B)
#define MATH2 (128 * ASTR)      // halfs per matrix per stage (5120)
#define MATB2 (MATH2 * 2)       // 10240 bytes
#define GEMM_SMEM (4 * MATB2)   // 40960

__device__ __forceinline__ void g_load_stage(
    uint32_t sbase, int buf,
    const __half* __restrict__ X, const __half* __restrict__ W,
    int m0, int n0, int k0, int t)
{
    uint32_t aB = sbase + (uint32_t)(buf * 2) * MATB2;
    uint32_t bB = aB + MATB2;
    #pragma unroll
    for (int i = 0; i < 2; ++i) {
        int cid = t + (i << 8);          // 0..511
        int r = cid >> 2;                // row 0..127
        int c = cid & 3;                 // 16B chunk (8 halfs)
        uint32_t off = (uint32_t)r * (ASTR * 2) + (uint32_t)c * 16;
        cp16(aB + off, X + (size_t)(m0 + r) * HID + k0 + (c << 3));
        cp16(bB + off, W + (size_t)(n0 + r) * HID + k0 + (c << 3));
    }
}

template <int MODE>
__global__ __launch_bounds__(256, 2) void gemm_h(
    const __half* __restrict__ X, const __half* __restrict__ W,
    const float* __restrict__ bias, void* __restrict__ outv, float oscale)
{
    extern __shared__ __align__(16) __half hsm[];
    const uint32_t sbase = smem_u32(hsm);

    const int t    = threadIdx.x;
    const int wid  = t >> 5;
    const int lane = t & 31;
    const int wr   = (wid >> 2) << 6;   // 0/64
    const int wc   = (wid & 3) << 5;    // 0/32/64/96
    const int m0   = blockIdx.y * TBM;
    const int n0   = blockIdx.x * TBN;
    const int lr   = lane >> 2;
    const int lc   = lane & 3;

    float acc[4][4][4] = {};

    g_load_stage(sbase, 0, X, W, m0, n0, 0, t);
    CP_COMMIT();
    g_load_stage(sbase, 1, X, W, m0, n0, TBK, t);
    CP_COMMIT();

    for (int s = 0; s < KSTAGES; ++s) {
        const int buf = s & 1;
        cp_wait<1>();
        __syncthreads();

        const __half* sA = hsm + (size_t)(buf * 2) * MATH2;
        const __half* sB = sA + MATH2;

        #pragma unroll
        for (int kk = 0; kk < 2; ++kk) {
            const int ko = (kk << 4) + (lc << 1);
            uint32_t af[4][4];
            #pragma unroll
            for (int mi = 0; mi < 4; ++mi) {
                const int r = wr + (mi << 4) + lr;
                af[mi][0] = *(const uint32_t*)&sA[r * ASTR + ko];
                af[mi][1] = *(const uint32_t*)&sA[(r + 8) * ASTR + ko];
                af[mi][2] = *(const uint32_t*)&sA[r * ASTR + ko + 8];
                af[mi][3] = *(const uint32_t*)&sA[(r + 8) * ASTR + ko + 8];
            }
            uint32_t bf[4][2];
            #pragma unroll
            for (int ni = 0; ni < 4; ++ni) {
                const int n = wc + (ni << 3) + lr;
                bf[ni][0] = *(const uint32_t*)&sB[n * ASTR + ko];
                bf[ni][1] = *(const uint32_t*)&sB[n * ASTR + ko + 8];
            }
            #pragma unroll
            for (int mi = 0; mi < 4; ++mi)
                #pragma unroll
                for (int ni = 0; ni < 4; ++ni)
                    mma_f16(acc[mi][ni][0], acc[mi][ni][1],
                            acc[mi][ni][2], acc[mi][ni][3],
                            af[mi][0], af[mi][1], af[mi][2], af[mi][3],
                            bf[ni][0], bf[ni][1]);
        }

        __syncthreads();
        if (s + 2 < KSTAGES) {
            g_load_stage(sbase, buf, X, W, m0, n0, (s + 2) * TBK, t);
            CP_COMMIT();
        }
    }

    #pragma unroll
    for (int mi = 0; mi < 4; ++mi) {
        #pragma unroll
        for (int ni = 0; ni < 4; ++ni) {
            const int row = m0 + wr + (mi << 4) + lr;
            const int col = n0 + wc + (ni << 3) + (lc << 1);
            float2 b01 = *(const float2*)&bias[col];
            float v00 = acc[mi][ni][0] + b01.x;
            float v01 = acc[mi][ni][1] + b01.y;
            float v10 = acc[mi][ni][2] + b01.x;
            float v11 = acc[mi][ni][3] + b01.y;
            if (MODE == 0) {
                float* out = (float*)outv;
                *(float2*)&out[(size_t)row * HID + col] = make_float2(v00, v01);
                *(float2*)&out[(size_t)(row + 8) * HID + col] = make_float2(v10, v11);
            } else if (MODE == 1) {
                __half* out = (__half*)outv;
                *(uint32_t*)&out[(size_t)row * HID + col] =
                    pack_h2(oscale * v00, oscale * v01);
                *(uint32_t*)&out[(size_t)(row + 8) * HID + col] =
                    pack_h2(oscale * v10, oscale * v11);
            } else {
                // MODE 2: transposed V store: g_vt[(b*NH+h)*HD+d][seq]
                __half* out = (__half*)outv;
                const int b0i = row >> 11, s0 = row & 2047;
                const int b1i = (row + 8) >> 11, s1 = (row + 8) & 2047;
                const int h0 = col >> 6, d0 = col & 63;
                const int h1 = (col + 1) >> 6, d1 = (col + 1) & 63;
                out[((size_t)(b0i * NH + h0) * HD + d0) * SEQ + s0] = __float2half(v00);
                out[((size_t)(b0i * NH + h1) * HD + d1) * SEQ + s0] = __float2half(v01);
                out[((size_t)(b1i * NH + h0) * HD + d0) * SEQ + s1] = __float2half(v10);
                out[((size_t)(b1i * NH + h1) * HD + d1) * SEQ + s1] = __float2half(v11);
            }
        }
    }
}

// ============================================================================
// Flash attention fp16 mma. CTA = (b, h, 64-q tile); 4 warps x 16 q-rows.
// K-tile = 64 keys double buffered. Q pre-scaled (0.125) half in g_q.
// smem halfs: sK[2][64*72] @0, sVt[2][64*72] @9216, sP[4][16*72] @18432
// ============================================================================
#define QT    64
#define ATHR  128
#define KT    64
#define NKT   (SEQ / KT)          // 32
#define HSTR  72                  // halfs per smem row (144B)
#define KSTG2 (KT * HSTR)         // 4608 halfs
#define VBASE2 (2 * KSTG2)        // 9216
#define PBASE2 (VBASE2 + 2 * KSTG2) // 18432
#define PWARP2 (16 * HSTR)        // 1152
#define ATT_SMEM_BYTES ((PBASE2 + 4 * PWARP2) * 2)  // 46080

__device__ __forceinline__ void a_load_kv(
    uint32_t sbase, int buf, int b, int h, int k0, int t)
{
    const uint32_t kB = sbase + (uint32_t)buf * (KSTG2 * 2);
    const uint32_t vB = sbase + (uint32_t)(VBASE2 + buf * KSTG2) * 2;
    #pragma unroll
    for (int i = 0; i < 4; ++i) {
        int cid = t + (i << 7);      // 0..511
        int r = cid >> 3;            // row 0..63
        int c = cid & 7;             // 16B chunk (8 halfs)
        // K: [seq][hid] natural
        cp16(kB + (uint32_t)r * (HSTR * 2) + (uint32_t)c * 16,
             g_k + (size_t)(b * SEQ + k0 + r) * HID + h * HD + (c << 3));
        // Vt: [(b*NH+h)*HD+d][seq]
        cp16(vB + (uint32_t)r * (HSTR * 2) + (uint32_t)c * 16,
             g_vt + ((size_t)(b * NH + h) * HD + r) * SEQ + k0 + (c << 3));
    }
}

__global__ __launch_bounds__(ATHR, 3) void attn_mma()
{
    extern __shared__ __align__(16) __half hsm[];
    const uint32_t sbase = smem_u32(hsm);

    const int t    = threadIdx.x;
    const int wid  = t >> 5;
    const int lane = t & 31;
    const int lr   = lane >> 2;
    const int lc   = lane & 3;

    const int b  = blockIdx.z;
    const int h  = blockIdx.y;
    const int q0 = blockIdx.x * QT;
    const int wq = wid << 4;

    // Q fragments (pre-scaled half): 4 k16-steps x 4 regs
    uint32_t qf[4][4];
    {
        const __half* Qg = g_q + (size_t)(b * SEQ + q0 + wq) * HID + h * HD;
        #pragma unroll
        for (int ks = 0; ks < 4; ++ks) {
            const int ko = (ks << 4) + (lc << 1);
            qf[ks][0] = *(const uint32_t*)&Qg[(size_t)lr * HID + ko];
            qf[ks][1] = *(const uint32_t*)&Qg[(size_t)(lr + 8) * HID + ko];
            qf[ks][2] = *(const uint32_t*)&Qg[(size_t)lr * HID + ko + 8];
            qf[ks][3] = *(const uint32_t*)&Qg[(size_t)(lr + 8) * HID + ko + 8];
        }
    }

    float O[8][4] = {};
    float mrow[2] = {-1e30f, -1e30f};
    float lrow[2] = {0.f, 0.f};

    a_load_kv(sbase, 0, b, h, 0, t);
    CP_COMMIT();
    a_load_kv(sbase, 1, b, h, KT, t);
    CP_COMMIT();

    __half* sPw = hsm + PBASE2 + wid * PWARP2;

    for (int kt = 0; kt < NKT; ++kt) {
        const int buf = kt & 1;
        cp_wait<1>();
        __syncthreads();

        const __half* sK = hsm + buf * KSTG2;
        const __half* sV = hsm + VBASE2 + buf * KSTG2;

        // ---- S = Qs @ K^T : B-frag = K[n][k..k+1] half2 (contiguous) ----
        float S[8][4] = {};
        #pragma unroll
        for (int ks = 0; ks < 4; ++ks) {
            const int ko = (ks << 4) + (lc << 1);
            #pragma unroll
            for (int nt = 0; nt < 8; ++nt) {
                const int n = (nt << 3) + lr;
                uint32_t b0 = *(const uint32_t*)&sK[n * HSTR + ko];
                uint32_t b1 = *(const uint32_t*)&sK[n * HSTR + ko + 8];
                mma_f16(S[nt][0], S[nt][1], S[nt][2], S[nt][3],
                        qf[ks][0], qf[ks][1], qf[ks][2], qf[ks][3], b0, b1);
            }
        }

        // ---- online softmax on fragments ----
        #pragma unroll
        for (int r = 0; r < 2; ++r) {
            const int e0 = r << 1, e1 = e0 + 1;
            float mt = -1e30f;
            #pragma unroll
            for (int nt = 0; nt < 8; ++nt)
                mt = fmaxf(mt, fmaxf(S[nt][e0], S[nt][e1]));
            mt = fmaxf(mt, __shfl_xor_sync(0xffffffffu, mt, 1));
            mt = fmaxf(mt, __shfl_xor_sync(0xffffffffu, mt, 2));
            float mnew = fmaxf(mrow[r], mt);
            float corr = __expf(mrow[r] - mnew);
            float rs = 0.f;
            #pragma unroll
            for (int nt = 0; nt < 8; ++nt) {
                float p0 = __expf(S[nt][e0] - mnew);
                float p1 = __expf(S[nt][e1] - mnew);
                S[nt][e0] = p0; S[nt][e1] = p1;
                rs += p0 + p1;
            }
            rs += __shfl_xor_sync(0xffffffffu, rs, 1);
            rs += __shfl_xor_sync(0xffffffffu, rs, 2);
            lrow[r] = lrow[r] * corr + rs;
            mrow[r] = mnew;
            #pragma unroll
            for (int nt = 0; nt < 8; ++nt) {
                O[nt][e0] *= corr;
                O[nt][e1] *= corr;
            }
        }

        // ---- P -> per-warp smem as half2 (C-frag pairs are contiguous) ----
        #pragma unroll
        for (int nt = 0; nt < 8; ++nt) {
            const int col = (nt << 3) + (lc << 1);
            *(uint32_t*)&sPw[lr * HSTR + col]       = pack_h2(S[nt][0], S[nt][1]);
            *(uint32_t*)&sPw[(lr + 8) * HSTR + col] = pack_h2(S[nt][2], S[nt][3]);
        }
        __syncwarp();

        // ---- O += P @ V : A-frag from sPw, B-frag = Vt[n][k..k+1] half2 ----
        #pragma unroll
        for (int ks = 0; ks < 4; ++ks) {
            const int ko = (ks << 4) + (lc << 1);
            uint32_t a0 = *(const uint32_t*)&sPw[lr * HSTR + ko];
            uint32_t a1 = *(const uint32_t*)&sPw[(lr + 8) * HSTR + ko];
            uint32_t a2 = *(const uint32_t*)&sPw[lr * HSTR + ko + 8];
            uint32_t a3 = *(const uint32_t*)&sPw[(lr + 8) * HSTR + ko + 8];
            #pragma unroll
            for (int nt = 0; nt < 8; ++nt) {
                const int n = (nt << 3) + lr;
                uint32_t b0 = *(const uint32_t*)&sV[n * HSTR + ko];
                uint32_t b1 = *(const uint32_t*)&sV[n * HSTR + ko + 8];
                mma_f16(O[nt][0], O[nt][1], O[nt][2], O[nt][3],
                        a0, a1, a2, a3, b0, b1);
            }
        }

        __syncthreads();
        if (kt + 2 < NKT) {
            a_load_kv(sbase, buf, b, h, (kt + 2) * KT, t);
            CP_COMMIT();
        }
    }

    // ---- normalize + store half (input to O-projection) ----
    const float inv0 = 1.f / lrow[0];
    const float inv1 = 1.f / lrow[1];
    __half* Og = g_att + (size_t)(b * SEQ + q0 + wq) * HID + h * HD;
    #pragma unroll
    for (int nt = 0; nt < 8; ++nt) {
        const int col = (nt << 3) + (lc << 1);
        *(uint32_t*)&Og[(size_t)lr * HID + col] =
            pack_h2(O[nt][0] * inv0, O[nt][1] * inv0);
        *(uint32_t*)&Og[(size_t)(lr + 8) * HID + col] =
            pack_h2(O[nt][2] * inv1, O[nt][3] * inv1);
    }
}

// ---------------- launch ----------------------------------------------------
extern "C" void kernel_launch(void* const* d_in, const int* in_sizes, int n_in,
                              void* d_out, int out_size)
{
    const float* hs = (const float*)d_in[0];
    const float* wq = (const float*)d_in[1];
    const float* bq = (const float*)d_in[2];
    const float* wk = (const float*)d_in[3];
    const float* bk = (const float*)d_in[4];
    const float* wv = (const float*)d_in[5];
    const float* bv = (const float*)d_in[6];
    const float* wo = (const float*)d_in[7];
    const float* bo = (const float*)d_in[8];
    float* out = (float*)d_out;

    __half *qp, *kp, *vtp, *ap, *hp, *wqp, *wkp, *wvp, *wop;
    cudaGetSymbolAddress((void**)&qp, g_q);
    cudaGetSymbolAddress((void**)&kp, g_k);
    cudaGetSymbolAddress((void**)&vtp, g_vt);
    cudaGetSymbolAddress((void**)&ap, g_att);
    cudaGetSymbolAddress((void**)&hp, g_hs);
    cudaGetSymbolAddress((void**)&wqp, g_wq);
    cudaGetSymbolAddress((void**)&wkp, g_wk);
    cudaGetSymbolAddress((void**)&wvp, g_wv);
    cudaGetSymbolAddress((void**)&wop, g_wo);

    cudaFuncSetAttribute(gemm_h<0>, cudaFuncAttributeMaxDynamicSharedMemorySize, GEMM_SMEM);
    cudaFuncSetAttribute(gemm_h<1>, cudaFuncAttributeMaxDynamicSharedMemorySize, GEMM_SMEM);
    cudaFuncSetAttribute(gemm_h<2>, cudaFuncAttributeMaxDynamicSharedMemorySize, GEMM_SMEM);
    cudaFuncSetAttribute(attn_mma, cudaFuncAttributeMaxDynamicSharedMemorySize, ATT_SMEM_BYTES);

    // convert inputs to half
    conv_h<<<(MROWS * HID / 4) / 256, 256>>>((const float4*)hs, (__half2*)hp);
    conv_h<<<(HID * HID / 4) / 256, 256>>>((const float4*)wq, (__half2*)wqp);
    conv_h<<<(HID * HID / 4) / 256, 256>>>((const float4*)wk, (__half2*)wkp);
    conv_h<<<(HID * HID / 4) / 256, 256>>>((const float4*)wv, (__half2*)wvp);
    conv_h<<<(HID * HID / 4) / 256, 256>>>((const float4*)wo, (__half2*)wop);

    dim3 ggrid(HID / TBN, MROWS / TBM);  // (8, 32)
    gemm_h<1><<<ggrid, 256, GEMM_SMEM>>>(hp, wqp, bq, qp, 0.125f);
    gemm_h<1><<<ggrid, 256, GEMM_SMEM>>>(hp, wkp, bk, kp, 1.0f);
    gemm_h<2><<<ggrid, 256, GEMM_SMEM>>>(hp, wvp, bv, vtp, 1.0f);

    dim3 agrid(SEQ / QT, NH, BATCH);     // (32, 16, 2)
    attn_mma<<<agrid, ATHR, ATT_SMEM_BYTES>>>();

    gemm_h<0><<<ggrid, 256, GEMM_SMEM>>>(ap, wop, bo, out, 1.0f);
}

// round 7
// speedup vs baseline: 7.3276x; 1.1324x over previous
#include <cuda_runtime.h>
#include <cuda_fp16.h>
#include <math.h>
#include <stdint.h>

// Problem constants
#define BATCH 2
#define SEQ   2048
#define HID   1024
#define NH    16
#define HD    64
#define MROWS (BATCH * SEQ)   // 4096

// Q pre-scale: HD^-0.5 * log2(e)  (softmax done in exp2 domain)
#define QSCALE (0.125f * 1.44269504088896f)

// ---------------- scratch (static device globals; no runtime alloc) ----------
__device__ __half g_q[MROWS * HID];      // pre-scaled by QSCALE
__device__ __half g_k[MROWS * HID];      // [seq][hid]
__device__ __half g_vt[MROWS * HID];     // [(b*NH+h)*HD+d][seq]
__device__ __half g_att[MROWS * HID];    // [seq][hid]
__device__ __half g_hs[MROWS * HID];
__device__ __half g_wqkv[3 * HID * HID]; // rows: [wq; wk; wv]
__device__ __half g_wo[HID * HID];
__device__ float  g_bqkv[3 * HID];

// ============================================================================
// helpers
// ============================================================================
__device__ __forceinline__ void cp16(uint32_t s, const void* g) {
    asm volatile("cp.async.cg.shared.global [%0], [%1], 16;" :: "r"(s), "l"(g));
}
#define CP_COMMIT() asm volatile("cp.async.commit_group;" ::: "memory")
template <int N>
__device__ __forceinline__ void cp_wait() {
    asm volatile("cp.async.wait_group %0;" :: "n"(N) : "memory");
}
__device__ __forceinline__ uint32_t smem_u32(const void* p) {
    uint32_t a;
    asm("{ .reg .u64 t; cvta.to.shared.u64 t, %1; cvt.u32.u64 %0, t; }"
        : "=r"(a) : "l"(p));
    return a;
}
__device__ __forceinline__ void mma_f16(
    float& c0, float& c1, float& c2, float& c3,
    uint32_t a0, uint32_t a1, uint32_t a2, uint32_t a3,
    uint32_t b0, uint32_t b1)
{
    asm volatile(
        "mma.sync.aligned.m16n8k16.row.col.f32.f16.f16.f32 "
        "{%0,%1,%2,%3}, {%4,%5,%6,%7}, {%8,%9}, {%0,%1,%2,%3};"
        : "+f"(c0), "+f"(c1), "+f"(c2), "+f"(c3)
        : "r"(a0), "r"(a1), "r"(a2), "r"(a3), "r"(b0), "r"(b1));
}
__device__ __forceinline__ void ldsm4(
    uint32_t& r0, uint32_t& r1, uint32_t& r2, uint32_t& r3, uint32_t a)
{
    asm volatile("ldmatrix.sync.aligned.m8n8.x4.shared.b16 {%0,%1,%2,%3}, [%4];"
                 : "=r"(r0), "=r"(r1), "=r"(r2), "=r"(r3) : "r"(a));
}
__device__ __forceinline__ uint32_t pack_h2(float a, float b) {
    __half2 h = __floats2half2_rn(a, b);
    return *(uint32_t*)&h;
}
__device__ __forceinline__ float ex2(float x) {
    float y;
    asm("ex2.approx.f32 %0, %1;" : "=f"(y) : "f"(x));
    return y;
}

// ============================================================================
// conversion kernels
// ============================================================================
__global__ void conv_h(const float4* __restrict__ in, __half2* __restrict__ out) {
    int i = blockIdx.x * blockDim.x + threadIdx.x;
    float4 v = in[i];
    out[2 * i]     = __floats2half2_rn(v.x, v.y);
    out[2 * i + 1] = __floats2half2_rn(v.z, v.w);
}

__global__ void conv_w4(const float4* __restrict__ wq, const float4* __restrict__ wk,
                        const float4* __restrict__ wv, const float4* __restrict__ wo,
                        __half2* __restrict__ wqkv, __half2* __restrict__ woh)
{
    int i = blockIdx.x * blockDim.x + threadIdx.x;   // 0 .. 4*2^18-1
    int seg = i >> 18;
    int off = i & 0x3FFFF;
    const float4* src = seg == 0 ? wq : seg == 1 ? wk : seg == 2 ? wv : wo;
    float4 v = src[off];
    __half2 h0 = __floats2half2_rn(v.x, v.y);
    __half2 h1 = __floats2half2_rn(v.z, v.w);
    if (seg < 3) { wqkv[2 * i] = h0; wqkv[2 * i + 1] = h1; }
    else         { woh[2 * off] = h0; woh[2 * off + 1] = h1; }
}

__global__ void conv_b(const float* __restrict__ bq, const float* __restrict__ bk,
                       const float* __restrict__ bv, float* __restrict__ dst)
{
    int i = blockIdx.x * blockDim.x + threadIdx.x;   // 0..3071
    const float* s = i < 1024 ? bq : i < 2048 ? bk : bv;
    dst[i] = s[i & 1023];
}

// ============================================================================
// fp16 GEMM mainloop (shared): acc[128,128] = X-tile @ W-tile^T, ldmatrix frags
// MODE 0: out f32 = acc + bias (O-projection)
// MODE 3: fused QKV epilogue, segment by global column
// ============================================================================
#define TBM 128
#define TBN 128
#define TBK 32
#define KSTAGES (HID / TBK)     // 32
#define ASTR 40                 // halfs per smem row (80B)
#define MATH2 (128 * ASTR)
#define MATB2 (MATH2 * 2)       // 10240 bytes
#define GEMM_SMEM (4 * MATB2)   // 40960

__device__ __forceinline__ void g_load_stage(
    uint32_t sbase, int buf,
    const __half* __restrict__ X, const __half* __restrict__ W,
    int m0, int n0, int k0, int t)
{
    uint32_t aB = sbase + (uint32_t)(buf * 2) * MATB2;
    uint32_t bB = aB + MATB2;
    #pragma unroll
    for (int i = 0; i < 2; ++i) {
        int cid = t + (i << 8);
        int r = cid >> 2;
        int c = cid & 3;
        uint32_t off = (uint32_t)r * (ASTR * 2) + (uint32_t)c * 16;
        cp16(aB + off, X + (size_t)(m0 + r) * HID + k0 + (c << 3));
        cp16(bB + off, W + (size_t)(n0 + r) * HID + k0 + (c << 3));
    }
}

template <int MODE>
__global__ __launch_bounds__(256, 2) void gemm_h(
    const __half* __restrict__ X, const __half* __restrict__ W,
    const float* __restrict__ bias, void* __restrict__ outv)
{
    extern __shared__ __align__(16) __half hsm[];
    const uint32_t sbase = smem_u32(hsm);

    const int t    = threadIdx.x;
    const int wid  = t >> 5;
    const int lane = t & 31;
    const int wr   = (wid >> 2) << 6;
    const int wc   = (wid & 3) << 5;
    const int m0   = blockIdx.y * TBM;
    const int n0   = blockIdx.x * TBN;
    const int lr   = lane >> 2;
    const int lc   = lane & 3;

    // ldmatrix per-lane address components
    const int i8 = lane & 7, j4 = lane >> 3;
    const uint32_t aRow = (uint32_t)(((j4 & 1) << 3) + i8);
    const uint32_t aKo  = (uint32_t)((j4 >> 1) << 3);
    const uint32_t bRow = (uint32_t)(((j4 >> 1) << 3) + i8);
    const uint32_t bKo  = (uint32_t)((j4 & 1) << 3);

    float acc[4][4][4] = {};

    g_load_stage(sbase, 0, X, W, m0, n0, 0, t);
    CP_COMMIT();
    g_load_stage(sbase, 1, X, W, m0, n0, TBK, t);
    CP_COMMIT();

    for (int s = 0; s < KSTAGES; ++s) {
        const int buf = s & 1;
        if (s + 1 < KSTAGES) cp_wait<1>(); else cp_wait<0>();
        __syncthreads();

        const uint32_t aB = sbase + (uint32_t)(buf * 2) * MATB2;
        const uint32_t bB = aB + MATB2;

        #pragma unroll
        for (int kk = 0; kk < 2; ++kk) {
            const uint32_t ko = (uint32_t)(kk << 4);
            uint32_t af[4][4];
            #pragma unroll
            for (int mi = 0; mi < 4; ++mi)
                ldsm4(af[mi][0], af[mi][1], af[mi][2], af[mi][3],
                      aB + (((uint32_t)(wr + (mi << 4)) + aRow) * ASTR + ko + aKo) * 2);
            uint32_t bf[4][2];
            #pragma unroll
            for (int p = 0; p < 2; ++p)
                ldsm4(bf[2 * p][0], bf[2 * p][1], bf[2 * p + 1][0], bf[2 * p + 1][1],
                      bB + (((uint32_t)(wc + (p << 4)) + bRow) * ASTR + ko + bKo) * 2);
            #pragma unroll
            for (int mi = 0; mi < 4; ++mi)
                #pragma unroll
                for (int ni = 0; ni < 4; ++ni)
                    mma_f16(acc[mi][ni][0], acc[mi][ni][1],
                            acc[mi][ni][2], acc[mi][ni][3],
                            af[mi][0], af[mi][1], af[mi][2], af[mi][3],
                            bf[ni][0], bf[ni][1]);
        }

        __syncthreads();
        if (s + 2 < KSTAGES) {
            g_load_stage(sbase, buf, X, W, m0, n0, (s + 2) * TBK, t);
            CP_COMMIT();
        }
    }

    const int seg = n0 >> 10;   // MODE 3 segment (uniform per CTA)

    #pragma unroll
    for (int mi = 0; mi < 4; ++mi) {
        #pragma unroll
        for (int ni = 0; ni < 4; ++ni) {
            const int row = m0 + wr + (mi << 4) + lr;
            const int col = n0 + wc + (ni << 3) + (lc << 1);
            float2 b01 = *(const float2*)&bias[col];
            float v00 = acc[mi][ni][0] + b01.x;
            float v01 = acc[mi][ni][1] + b01.y;
            float v10 = acc[mi][ni][2] + b01.x;
            float v11 = acc[mi][ni][3] + b01.y;
            if (MODE == 0) {
                float* out = (float*)outv;
                *(float2*)&out[(size_t)row * HID + col] = make_float2(v00, v01);
                *(float2*)&out[(size_t)(row + 8) * HID + col] = make_float2(v10, v11);
            } else {
                const int c = col & 1023;
                if (seg == 0) {          // Q, scaled
                    *(uint32_t*)&g_q[(size_t)row * HID + c] =
                        pack_h2(QSCALE * v00, QSCALE * v01);
                    *(uint32_t*)&g_q[(size_t)(row + 8) * HID + c] =
                        pack_h2(QSCALE * v10, QSCALE * v11);
                } else if (seg == 1) {   // K natural
                    *(uint32_t*)&g_k[(size_t)row * HID + c] = pack_h2(v00, v01);
                    *(uint32_t*)&g_k[(size_t)(row + 8) * HID + c] = pack_h2(v10, v11);
                } else {                 // V transposed
                    const int b0i = row >> 11, s0 = row & 2047;
                    const int b1i = (row + 8) >> 11, s1 = (row + 8) & 2047;
                    const int h0 = c >> 6, d0 = c & 63;
                    const int h1 = (c + 1) >> 6, d1 = (c + 1) & 63;
                    g_vt[((size_t)(b0i * NH + h0) * HD + d0) * SEQ + s0] = __float2half(v00);
                    g_vt[((size_t)(b0i * NH + h1) * HD + d1) * SEQ + s0] = __float2half(v01);
                    g_vt[((size_t)(b1i * NH + h0) * HD + d0) * SEQ + s1] = __float2half(v10);
                    g_vt[((size_t)(b1i * NH + h1) * HD + d1) * SEQ + s1] = __float2half(v11);
                }
            }
        }
    }
}

// ============================================================================
// Flash attention fp16 mma + ldmatrix. CTA = (b,h,64-q tile); 4 warps.
// ============================================================================
#define QT    64
#define ATHR  128
#define KT    64
#define NKT   (SEQ / KT)            // 32
#define HSTR  72                    // halfs per smem row (144B)
#define KSTG2 (KT * HSTR)           // 4608 halfs
#define VBASE2 (2 * KSTG2)          // 9216
#define PBASE2 (VBASE2 + 2 * KSTG2) // 18432
#define PWARP2 (16 * HSTR)          // 1152
#define ATT_SMEM_BYTES ((PBASE2 + 4 * PWARP2) * 2)  // 46080

__device__ __forceinline__ void a_load_kv(
    uint32_t sbase, int buf, int b, int h, int k0, int t)
{
    const uint32_t kB = sbase + (uint32_t)buf * (KSTG2 * 2);
    const uint32_t vB = sbase + (uint32_t)(VBASE2 + buf * KSTG2) * 2;
    #pragma unroll
    for (int i = 0; i < 4; ++i) {
        int cid = t + (i << 7);
        int r = cid >> 3;
        int c = cid & 7;
        cp16(kB + (uint32_t)r * (HSTR * 2) + (uint32_t)c * 16,
             g_k + (size_t)(b * SEQ + k0 + r) * HID + h * HD + (c << 3));
        cp16(vB + (uint32_t)r * (HSTR * 2) + (uint32_t)c * 16,
             g_vt + ((size_t)(b * NH + h) * HD + r) * SEQ + k0 + (c << 3));
    }
}

__global__ __launch_bounds__(ATHR, 3) void attn_mma()
{
    extern __shared__ __align__(16) __half hsm[];
    const uint32_t sbase = smem_u32(hsm);

    const int t    = threadIdx.x;
    const int wid  = t >> 5;
    const int lane = t & 31;
    const int lr   = lane >> 2;
    const int lc   = lane & 3;

    const int i8 = lane & 7, j4 = lane >> 3;
    const uint32_t aRow = (uint32_t)(((j4 & 1) << 3) + i8);
    const uint32_t aKo  = (uint32_t)((j4 >> 1) << 3);
    const uint32_t bRow = (uint32_t)(((j4 >> 1) << 3) + i8);
    const uint32_t bKo  = (uint32_t)((j4 & 1) << 3);

    const int b  = blockIdx.z;
    const int h  = blockIdx.y;
    const int q0 = blockIdx.x * QT;
    const int wq = wid << 4;

    // Q fragments (pre-scaled by QSCALE in projection epilogue)
    uint32_t qf[4][4];
    {
        const __half* Qg = g_q + (size_t)(b * SEQ + q0 + wq) * HID + h * HD;
        #pragma unroll
        for (int ks = 0; ks < 4; ++ks) {
            const int ko = (ks << 4) + (lc << 1);
            qf[ks][0] = *(const uint32_t*)&Qg[(size_t)lr * HID + ko];
            qf[ks][1] = *(const uint32_t*)&Qg[(size_t)(lr + 8) * HID + ko];
            qf[ks][2] = *(const uint32_t*)&Qg[(size_t)lr * HID + ko + 8];
            qf[ks][3] = *(const uint32_t*)&Qg[(size_t)(lr + 8) * HID + ko + 8];
        }
    }

    float O[8][4] = {};
    float mrow[2] = {-1e30f, -1e30f};   // log2 domain
    float lrow[2] = {0.f, 0.f};

    a_load_kv(sbase, 0, b, h, 0, t);
    CP_COMMIT();
    a_load_kv(sbase, 1, b, h, KT, t);
    CP_COMMIT();

    const uint32_t pB = sbase + (uint32_t)(PBASE2 + wid * PWARP2) * 2;
    __half* sPw = hsm + PBASE2 + wid * PWARP2;

    for (int kt = 0; kt < NKT; ++kt) {
        const int buf = kt & 1;
        if (kt + 1 < NKT) cp_wait<1>(); else cp_wait<0>();
        __syncthreads();

        const uint32_t kB = sbase + (uint32_t)buf * (KSTG2 * 2);
        const uint32_t vB = sbase + (uint32_t)(VBASE2 + buf * KSTG2) * 2;

        // ---- S = Qs @ K^T (exp2 domain) ----
        float S[8][4] = {};
        #pragma unroll
        for (int ks = 0; ks < 4; ++ks) {
            const uint32_t ko = (uint32_t)(ks << 4);
            #pragma unroll
            for (int p = 0; p < 4; ++p) {
                uint32_t b0, b1, b2, b3;
                ldsm4(b0, b1, b2, b3,
                      kB + (((uint32_t)(p << 4) + bRow) * HSTR + ko + bKo) * 2);
                mma_f16(S[2*p][0], S[2*p][1], S[2*p][2], S[2*p][3],
                        qf[ks][0], qf[ks][1], qf[ks][2], qf[ks][3], b0, b1);
                mma_f16(S[2*p+1][0], S[2*p+1][1], S[2*p+1][2], S[2*p+1][3],
                        qf[ks][0], qf[ks][1], qf[ks][2], qf[ks][3], b2, b3);
            }
        }

        // ---- online softmax (exp2 domain) ----
        #pragma unroll
        for (int r = 0; r < 2; ++r) {
            const int e0 = r << 1, e1 = e0 + 1;
            float mt = -1e30f;
            #pragma unroll
            for (int nt = 0; nt < 8; ++nt)
                mt = fmaxf(mt, fmaxf(S[nt][e0], S[nt][e1]));
            mt = fmaxf(mt, __shfl_xor_sync(0xffffffffu, mt, 1));
            mt = fmaxf(mt, __shfl_xor_sync(0xffffffffu, mt, 2));
            float mnew = fmaxf(mrow[r], mt);
            float corr = ex2(mrow[r] - mnew);
            float rs = 0.f;
            #pragma unroll
            for (int nt = 0; nt < 8; ++nt) {
                float p0 = ex2(S[nt][e0] - mnew);
                float p1 = ex2(S[nt][e1] - mnew);
                S[nt][e0] = p0; S[nt][e1] = p1;
                rs += p0 + p1;
            }
            rs += __shfl_xor_sync(0xffffffffu, rs, 1);
            rs += __shfl_xor_sync(0xffffffffu, rs, 2);
            lrow[r] = lrow[r] * corr + rs;
            mrow[r] = mnew;
            #pragma unroll
            for (int nt = 0; nt < 8; ++nt) {
                O[nt][e0] *= corr;
                O[nt][e1] *= corr;
            }
        }

        // ---- P -> per-warp smem ----
        #pragma unroll
        for (int nt = 0; nt < 8; ++nt) {
            const int col = (nt << 3) + (lc << 1);
            *(uint32_t*)&sPw[lr * HSTR + col]       = pack_h2(S[nt][0], S[nt][1]);
            *(uint32_t*)&sPw[(lr + 8) * HSTR + col] = pack_h2(S[nt][2], S[nt][3]);
        }
        __syncwarp();

        // ---- O += P @ V ----
        #pragma unroll
        for (int ks = 0; ks < 4; ++ks) {
            const uint32_t ko = (uint32_t)(ks << 4);
            uint32_t a0, a1, a2, a3;
            ldsm4(a0, a1, a2, a3, pB + (aRow * HSTR + ko + aKo) * 2);
            #pragma unroll
            for (int p = 0; p < 4; ++p) {
                uint32_t v0, v1, v2, v3;
                ldsm4(v0, v1, v2, v3,
                      vB + (((uint32_t)(p << 4) + bRow) * HSTR + ko + bKo) * 2);
                mma_f16(O[2*p][0], O[2*p][1], O[2*p][2], O[2*p][3],
                        a0, a1, a2, a3, v0, v1);
                mma_f16(O[2*p+1][0], O[2*p+1][1], O[2*p+1][2], O[2*p+1][3],
                        a0, a1, a2, a3, v2, v3);
            }
        }

        __syncthreads();
        if (kt + 2 < NKT) {
            a_load_kv(sbase, buf, b, h, (kt + 2) * KT, t);
            CP_COMMIT();
        }
    }

    // ---- normalize + store half ----
    const float inv0 = 1.f / lrow[0];
    const float inv1 = 1.f / lrow[1];
    __half* Og = g_att + (size_t)(b * SEQ + q0 + wq) * HID + h * HD;
    #pragma unroll
    for (int nt = 0; nt < 8; ++nt) {
        const int col = (nt << 3) + (lc << 1);
        *(uint32_t*)&Og[(size_t)lr * HID + col] =
            pack_h2(O[nt][0] * inv0, O[nt][1] * inv0);
        *(uint32_t*)&Og[(size_t)(lr + 8) * HID + col] =
            pack_h2(O[nt][2] * inv1, O[nt][3] * inv1);
    }
}

// ---------------- launch ----------------------------------------------------
extern "C" void kernel_launch(void* const* d_in, const int* in_sizes, int n_in,
                              void* d_out, int out_size)
{
    const float* hs = (const float*)d_in[0];
    const float* wq = (const float*)d_in[1];
    const float* bq = (const float*)d_in[2];
    const float* wk = (const float*)d_in[3];
    const float* bk = (const float*)d_in[4];
    const float* wv = (const float*)d_in[5];
    const float* bv = (const float*)d_in[6];
    const float* wo = (const float*)d_in[7];
    const float* bo = (const float*)d_in[8];
    float* out = (float*)d_out;

    __half *hp, *wqkvp, *wop, *ap;
    float *bqkvp;
    cudaGetSymbolAddress((void**)&hp, g_hs);
    cudaGetSymbolAddress((void**)&wqkvp, g_wqkv);
    cudaGetSymbolAddress((void**)&wop, g_wo);
    cudaGetSymbolAddress((void**)&ap, g_att);
    cudaGetSymbolAddress((void**)&bqkvp, g_bqkv);

    cudaFuncSetAttribute(gemm_h<0>, cudaFuncAttributeMaxDynamicSharedMemorySize, GEMM_SMEM);
    cudaFuncSetAttribute(gemm_h<3>, cudaFuncAttributeMaxDynamicSharedMemorySize, GEMM_SMEM);
    cudaFuncSetAttribute(attn_mma, cudaFuncAttributeMaxDynamicSharedMemorySize, ATT_SMEM_BYTES);

    conv_h<<<(MROWS * HID / 4) / 256, 256>>>((const float4*)hs, (__half2*)hp);
    conv_w4<<<(4 * HID * HID / 4) / 256, 256>>>(
        (const float4*)wq, (const float4*)wk, (const float4*)wv, (const float4*)wo,
        (__half2*)wqkvp, (__half2*)wop);
    conv_b<<<12, 256>>>(bq, bk, bv, bqkvp);

    dim3 qkvgrid(3 * HID / TBN, MROWS / TBM);  // (24, 32)
    gemm_h<3><<<qkvgrid, 256, GEMM_SMEM>>>(hp, wqkvp, bqkvp, nullptr);

    dim3 agrid(SEQ / QT, NH, BATCH);           // (32, 16, 2)
    attn_mma<<<agrid, ATHR, ATT_SMEM_BYTES>>>();

    dim3 ogrid(HID / TBN, MROWS / TBM);        // (8, 32)
    gemm_h<0><<<ogrid, 256, GEMM_SMEM>>>(ap, wop, bo, out);
}

// round 8
// speedup vs baseline: 7.4452x; 1.0161x over previous
#include <cuda_runtime.h>
#include <cuda_fp16.h>
#include <math.h>
#include <stdint.h>

// Problem constants
#define BATCH 2
#define SEQ   2048
#define HID   1024
#define NH    16
#define HD    64
#define MROWS (BATCH * SEQ)   // 4096

// Q pre-scale: HD^-0.5 * log2(e)  (softmax done in exp2 domain)
#define QSCALE (0.125f * 1.44269504088896f)

// ---------------- scratch (static device globals; no runtime alloc) ----------
__device__ __half g_q[MROWS * HID];      // pre-scaled by QSCALE
__device__ __half g_k[MROWS * HID];      // [seq][hid]
__device__ __half g_vt[MROWS * HID];     // [(b*NH+h)*HD+d][seq]
__device__ __half g_att[MROWS * HID];    // [seq][hid]
__device__ __half g_hs[MROWS * HID];
__device__ __half g_wqkv[3 * HID * HID]; // rows: [wq; wk; wv]
__device__ __half g_wo[HID * HID];
__device__ float  g_bqkv[3 * HID];

// ============================================================================
// helpers
// ============================================================================
__device__ __forceinline__ void cp16(uint32_t s, const void* g) {
    asm volatile("cp.async.cg.shared.global [%0], [%1], 16;" :: "r"(s), "l"(g));
}
#define CP_COMMIT() asm volatile("cp.async.commit_group;" ::: "memory")
template <int N>
__device__ __forceinline__ void cp_wait() {
    asm volatile("cp.async.wait_group %0;" :: "n"(N) : "memory");
}
__device__ __forceinline__ uint32_t smem_u32(const void* p) {
    uint32_t a;
    asm("{ .reg .u64 t; cvta.to.shared.u64 t, %1; cvt.u32.u64 %0, t; }"
        : "=r"(a) : "l"(p));
    return a;
}
__device__ __forceinline__ void mma_f16(
    float& c0, float& c1, float& c2, float& c3,
    uint32_t a0, uint32_t a1, uint32_t a2, uint32_t a3,
    uint32_t b0, uint32_t b1)
{
    asm volatile(
        "mma.sync.aligned.m16n8k16.row.col.f32.f16.f16.f32 "
        "{%0,%1,%2,%3}, {%4,%5,%6,%7}, {%8,%9}, {%0,%1,%2,%3};"
        : "+f"(c0), "+f"(c1), "+f"(c2), "+f"(c3)
        : "r"(a0), "r"(a1), "r"(a2), "r"(a3), "r"(b0), "r"(b1));
}
__device__ __forceinline__ void ldsm4(
    uint32_t& r0, uint32_t& r1, uint32_t& r2, uint32_t& r3, uint32_t a)
{
    asm volatile("ldmatrix.sync.aligned.m8n8.x4.shared.b16 {%0,%1,%2,%3}, [%4];"
                 : "=r"(r0), "=r"(r1), "=r"(r2), "=r"(r3) : "r"(a));
}
__device__ __forceinline__ uint32_t pack_h2(float a, float b) {
    __half2 h = __floats2half2_rn(a, b);
    return *(uint32_t*)&h;
}
__device__ __forceinline__ float ex2(float x) {
    float y;
    asm("ex2.approx.f32 %0, %1;" : "=f"(y) : "f"(x));
    return y;
}

// ============================================================================
// conversion kernels
// ============================================================================
__global__ void conv_h(const float4* __restrict__ in, __half2* __restrict__ out) {
    int i = blockIdx.x * blockDim.x + threadIdx.x;
    float4 v = in[i];
    out[2 * i]     = __floats2half2_rn(v.x, v.y);
    out[2 * i + 1] = __floats2half2_rn(v.z, v.w);
}

__global__ void conv_w4(const float4* __restrict__ wq, const float4* __restrict__ wk,
                        const float4* __restrict__ wv, const float4* __restrict__ wo,
                        __half2* __restrict__ wqkv, __half2* __restrict__ woh)
{
    int i = blockIdx.x * blockDim.x + threadIdx.x;
    int seg = i >> 18;
    int off = i & 0x3FFFF;
    const float4* src = seg == 0 ? wq : seg == 1 ? wk : seg == 2 ? wv : wo;
    float4 v = src[off];
    __half2 h0 = __floats2half2_rn(v.x, v.y);
    __half2 h1 = __floats2half2_rn(v.z, v.w);
    if (seg < 3) { wqkv[2 * i] = h0; wqkv[2 * i + 1] = h1; }
    else         { woh[2 * off] = h0; woh[2 * off + 1] = h1; }
}

__global__ void conv_b(const float* __restrict__ bq, const float* __restrict__ bk,
                       const float* __restrict__ bv, float* __restrict__ dst)
{
    int i = blockIdx.x * blockDim.x + threadIdx.x;
    const float* s = i < 1024 ? bq : i < 2048 ? bk : bv;
    dst[i] = s[i & 1023];
}

// ============================================================================
// fp16 GEMM: 3-stage cp.async ring, ONE barrier per stage.
// MODE 0: out f32 = acc + bias (O-projection)
// MODE 3: fused QKV epilogue, segment by global column
// ============================================================================
#define TBM 128
#define TBN 128
#define TBK 32
#define KSTAGES (HID / TBK)     // 32
#define ASTR 40                 // halfs per smem row (80B)
#define MATH2 (128 * ASTR)
#define MATB2 (MATH2 * 2)       // 10240 bytes
#define GSTAGES 3
#define GEMM_SMEM (GSTAGES * 2 * MATB2)   // 61440

__device__ __forceinline__ void g_load_stage(
    uint32_t sbase, int slot,
    const __half* __restrict__ X, const __half* __restrict__ W,
    int m0, int n0, int k0, int t)
{
    uint32_t aB = sbase + (uint32_t)(slot * 2) * MATB2;
    uint32_t bB = aB + MATB2;
    #pragma unroll
    for (int i = 0; i < 2; ++i) {
        int cid = t + (i << 8);
        int r = cid >> 2;
        int c = cid & 3;
        uint32_t off = (uint32_t)r * (ASTR * 2) + (uint32_t)c * 16;
        cp16(aB + off, X + (size_t)(m0 + r) * HID + k0 + (c << 3));
        cp16(bB + off, W + (size_t)(n0 + r) * HID + k0 + (c << 3));
    }
}

template <int MODE>
__global__ __launch_bounds__(256, 2) void gemm_h(
    const __half* __restrict__ X, const __half* __restrict__ W,
    const float* __restrict__ bias, void* __restrict__ outv)
{
    extern __shared__ __align__(16) __half hsm[];
    const uint32_t sbase = smem_u32(hsm);

    const int t    = threadIdx.x;
    const int wid  = t >> 5;
    const int lane = t & 31;
    const int wr   = (wid >> 2) << 6;
    const int wc   = (wid & 3) << 5;
    const int m0   = blockIdx.y * TBM;
    const int n0   = blockIdx.x * TBN;
    const int lr   = lane >> 2;
    const int lc   = lane & 3;

    const int i8 = lane & 7, j4 = lane >> 3;
    const uint32_t aRow = (uint32_t)(((j4 & 1) << 3) + i8);
    const uint32_t aKo  = (uint32_t)((j4 >> 1) << 3);
    const uint32_t bRow = (uint32_t)(((j4 >> 1) << 3) + i8);
    const uint32_t bKo  = (uint32_t)((j4 & 1) << 3);

    float acc[4][4][4] = {};

    g_load_stage(sbase, 0, X, W, m0, n0, 0, t);
    CP_COMMIT();
    g_load_stage(sbase, 1, X, W, m0, n0, TBK, t);
    CP_COMMIT();

    int slot = 0;
    for (int s = 0; s < KSTAGES; ++s) {
        if (s + 1 < KSTAGES) cp_wait<1>(); else cp_wait<0>();
        __syncthreads();

        // issue next-next stage loads first (slot (s+2)%3 was freed at iter s-1)
        if (s + 2 < KSTAGES) {
            int nslot = slot + 2; if (nslot >= GSTAGES) nslot -= GSTAGES;
            g_load_stage(sbase, nslot, X, W, m0, n0, (s + 2) * TBK, t);
            CP_COMMIT();
        }

        const uint32_t aB = sbase + (uint32_t)(slot * 2) * MATB2;
        const uint32_t bB = aB + MATB2;

        #pragma unroll
        for (int kk = 0; kk < 2; ++kk) {
            const uint32_t ko = (uint32_t)(kk << 4);
            uint32_t af[4][4];
            #pragma unroll
            for (int mi = 0; mi < 4; ++mi)
                ldsm4(af[mi][0], af[mi][1], af[mi][2], af[mi][3],
                      aB + (((uint32_t)(wr + (mi << 4)) + aRow) * ASTR + ko + aKo) * 2);
            uint32_t bf[4][2];
            #pragma unroll
            for (int p = 0; p < 2; ++p)
                ldsm4(bf[2 * p][0], bf[2 * p][1], bf[2 * p + 1][0], bf[2 * p + 1][1],
                      bB + (((uint32_t)(wc + (p << 4)) + bRow) * ASTR + ko + bKo) * 2);
            #pragma unroll
            for (int mi = 0; mi < 4; ++mi)
                #pragma unroll
                for (int ni = 0; ni < 4; ++ni)
                    mma_f16(acc[mi][ni][0], acc[mi][ni][1],
                            acc[mi][ni][2], acc[mi][ni][3],
                            af[mi][0], af[mi][1], af[mi][2], af[mi][3],
                            bf[ni][0], bf[ni][1]);
        }

        if (++slot >= GSTAGES) slot = 0;
    }

    const int seg = n0 >> 10;

    #pragma unroll
    for (int mi = 0; mi < 4; ++mi) {
        #pragma unroll
        for (int ni = 0; ni < 4; ++ni) {
            const int row = m0 + wr + (mi << 4) + lr;
            const int col = n0 + wc + (ni << 3) + (lc << 1);
            float2 b01 = *(const float2*)&bias[col];
            float v00 = acc[mi][ni][0] + b01.x;
            float v01 = acc[mi][ni][1] + b01.y;
            float v10 = acc[mi][ni][2] + b01.x;
            float v11 = acc[mi][ni][3] + b01.y;
            if (MODE == 0) {
                float* out = (float*)outv;
                *(float2*)&out[(size_t)row * HID + col] = make_float2(v00, v01);
                *(float2*)&out[(size_t)(row + 8) * HID + col] = make_float2(v10, v11);
            } else {
                const int c = col & 1023;
                if (seg == 0) {
                    *(uint32_t*)&g_q[(size_t)row * HID + c] =
                        pack_h2(QSCALE * v00, QSCALE * v01);
                    *(uint32_t*)&g_q[(size_t)(row + 8) * HID + c] =
                        pack_h2(QSCALE * v10, QSCALE * v11);
                } else if (seg == 1) {
                    *(uint32_t*)&g_k[(size_t)row * HID + c] = pack_h2(v00, v01);
                    *(uint32_t*)&g_k[(size_t)(row + 8) * HID + c] = pack_h2(v10, v11);
                } else {
                    const int b0i = row >> 11, s0 = row & 2047;
                    const int b1i = (row + 8) >> 11, s1 = (row + 8) & 2047;
                    const int h0 = c >> 6, d0 = c & 63;
                    const int h1 = (c + 1) >> 6, d1 = (c + 1) & 63;
                    g_vt[((size_t)(b0i * NH + h0) * HD + d0) * SEQ + s0] = __float2half(v00);
                    g_vt[((size_t)(b0i * NH + h1) * HD + d1) * SEQ + s0] = __float2half(v01);
                    g_vt[((size_t)(b1i * NH + h0) * HD + d0) * SEQ + s1] = __float2half(v10);
                    g_vt[((size_t)(b1i * NH + h1) * HD + d1) * SEQ + s1] = __float2half(v11);
                }
            }
        }
    }
}

// ============================================================================
// Flash attention: 3-stage KV ring, ONE barrier per tile.
// ============================================================================
#define QT    64
#define ATHR  128
#define KT    64
#define NKT   (SEQ / KT)            // 32
#define HSTR  72                    // halfs per smem row (144B)
#define KSTG2 (KT * HSTR)           // 4608 halfs per stage
#define ASTAGES 3
#define VBASE2 (ASTAGES * KSTG2)    // 13824
#define PBASE2 (VBASE2 + ASTAGES * KSTG2)  // 27648
#define PWARP2 (16 * HSTR)          // 1152
#define ATT_SMEM_BYTES ((PBASE2 + 4 * PWARP2) * 2)  // 64512

__device__ __forceinline__ void a_load_kv(
    uint32_t sbase, int slot, int b, int h, int k0, int t)
{
    const uint32_t kB = sbase + (uint32_t)slot * (KSTG2 * 2);
    const uint32_t vB = sbase + (uint32_t)(VBASE2 + slot * KSTG2) * 2;
    #pragma unroll
    for (int i = 0; i < 4; ++i) {
        int cid = t + (i << 7);
        int r = cid >> 3;
        int c = cid & 7;
        cp16(kB + (uint32_t)r * (HSTR * 2) + (uint32_t)c * 16,
             g_k + (size_t)(b * SEQ + k0 + r) * HID + h * HD + (c << 3));
        cp16(vB + (uint32_t)r * (HSTR * 2) + (uint32_t)c * 16,
             g_vt + ((size_t)(b * NH + h) * HD + r) * SEQ + k0 + (c << 3));
    }
}

__global__ __launch_bounds__(ATHR, 3) void attn_mma()
{
    extern __shared__ __align__(16) __half hsm[];
    const uint32_t sbase = smem_u32(hsm);

    const int t    = threadIdx.x;
    const int wid  = t >> 5;
    const int lane = t & 31;
    const int lr   = lane >> 2;
    const int lc   = lane & 3;

    const int i8 = lane & 7, j4 = lane >> 3;
    const uint32_t aRow = (uint32_t)(((j4 & 1) << 3) + i8);
    const uint32_t aKo  = (uint32_t)((j4 >> 1) << 3);
    const uint32_t bRow = (uint32_t)(((j4 >> 1) << 3) + i8);
    const uint32_t bKo  = (uint32_t)((j4 & 1) << 3);

    const int b  = blockIdx.z;
    const int h  = blockIdx.y;
    const int q0 = blockIdx.x * QT;
    const int wq = wid << 4;

    uint32_t qf[4][4];
    {
        const __half* Qg = g_q + (size_t)(b * SEQ + q0 + wq) * HID + h * HD;
        #pragma unroll
        for (int ks = 0; ks < 4; ++ks) {
            const int ko = (ks << 4) + (lc << 1);
            qf[ks][0] = *(const uint32_t*)&Qg[(size_t)lr * HID + ko];
            qf[ks][1] = *(const uint32_t*)&Qg[(size_t)(lr + 8) * HID + ko];
            qf[ks][2] = *(const uint32_t*)&Qg[(size_t)lr * HID + ko + 8];
            qf[ks][3] = *(const uint32_t*)&Qg[(size_t)(lr + 8) * HID + ko + 8];
        }
    }

    float O[8][4] = {};
    float mrow[2] = {-1e30f, -1e30f};
    float lrow[2] = {0.f, 0.f};

    a_load_kv(sbase, 0, b, h, 0, t);
    CP_COMMIT();
    a_load_kv(sbase, 1, b, h, KT, t);
    CP_COMMIT();

    const uint32_t pB = sbase + (uint32_t)(PBASE2 + wid * PWARP2) * 2;
    __half* sPw = hsm + PBASE2 + wid * PWARP2;

    int slot = 0;
    for (int kt = 0; kt < NKT; ++kt) {
        if (kt + 1 < NKT) cp_wait<1>(); else cp_wait<0>();
        __syncthreads();

        if (kt + 2 < NKT) {
            int nslot = slot + 2; if (nslot >= ASTAGES) nslot -= ASTAGES;
            a_load_kv(sbase, nslot, b, h, (kt + 2) * KT, t);
            CP_COMMIT();
        }

        const uint32_t kB = sbase + (uint32_t)slot * (KSTG2 * 2);
        const uint32_t vB = sbase + (uint32_t)(VBASE2 + slot * KSTG2) * 2;

        // ---- S = Qs @ K^T (exp2 domain) ----
        float S[8][4] = {};
        #pragma unroll
        for (int ks = 0; ks < 4; ++ks) {
            const uint32_t ko = (uint32_t)(ks << 4);
            #pragma unroll
            for (int p = 0; p < 4; ++p) {
                uint32_t b0, b1, b2, b3;
                ldsm4(b0, b1, b2, b3,
                      kB + (((uint32_t)(p << 4) + bRow) * HSTR + ko + bKo) * 2);
                mma_f16(S[2*p][0], S[2*p][1], S[2*p][2], S[2*p][3],
                        qf[ks][0], qf[ks][1], qf[ks][2], qf[ks][3], b0, b1);
                mma_f16(S[2*p+1][0], S[2*p+1][1], S[2*p+1][2], S[2*p+1][3],
                        qf[ks][0], qf[ks][1], qf[ks][2], qf[ks][3], b2, b3);
            }
        }

        // ---- online softmax (exp2 domain) ----
        #pragma unroll
        for (int r = 0; r < 2; ++r) {
            const int e0 = r << 1, e1 = e0 + 1;
            float mt = -1e30f;
            #pragma unroll
            for (int nt = 0; nt < 8; ++nt)
                mt = fmaxf(mt, fmaxf(S[nt][e0], S[nt][e1]));
            mt = fmaxf(mt, __shfl_xor_sync(0xffffffffu, mt, 1));
            mt = fmaxf(mt, __shfl_xor_sync(0xffffffffu, mt, 2));
            float mnew = fmaxf(mrow[r], mt);
            float corr = ex2(mrow[r] - mnew);
            float rs = 0.f;
            #pragma unroll
            for (int nt = 0; nt < 8; ++nt) {
                float p0 = ex2(S[nt][e0] - mnew);
                float p1 = ex2(S[nt][e1] - mnew);
                S[nt][e0] = p0; S[nt][e1] = p1;
                rs += p0 + p1;
            }
            rs += __shfl_xor_sync(0xffffffffu, rs, 1);
            rs += __shfl_xor_sync(0xffffffffu, rs, 2);
            lrow[r] = lrow[r] * corr + rs;
            mrow[r] = mnew;
            #pragma unroll
            for (int nt = 0; nt < 8; ++nt) {
                O[nt][e0] *= corr;
                O[nt][e1] *= corr;
            }
        }

        // ---- P -> per-warp smem ----
        #pragma unroll
        for (int nt = 0; nt < 8; ++nt) {
            const int col = (nt << 3) + (lc << 1);
            *(uint32_t*)&sPw[lr * HSTR + col]       = pack_h2(S[nt][0], S[nt][1]);
            *(uint32_t*)&sPw[(lr + 8) * HSTR + col] = pack_h2(S[nt][2], S[nt][3]);
        }
        __syncwarp();

        // ---- O += P @ V ----
        #pragma unroll
        for (int ks = 0; ks < 4; ++ks) {
            const uint32_t ko = (uint32_t)(ks << 4);
            uint32_t a0, a1, a2, a3;
            ldsm4(a0, a1, a2, a3, pB + (aRow * HSTR + ko + aKo) * 2);
            #pragma unroll
            for (int p = 0; p < 4; ++p) {
                uint32_t v0, v1, v2, v3;
                ldsm4(v0, v1, v2, v3,
                      vB + (((uint32_t)(p << 4) + bRow) * HSTR + ko + bKo) * 2);
                mma_f16(O[2*p][0], O[2*p][1], O[2*p][2], O[2*p][3],
                        a0, a1, a2, a3, v0, v1);
                mma_f16(O[2*p+1][0], O[2*p+1][1], O[2*p+1][2], O[2*p+1][3],
                        a0, a1, a2, a3, v2, v3);
            }
        }

        if (++slot >= ASTAGES) slot = 0;
    }

    // ---- normalize + store half ----
    const float inv0 = 1.f / lrow[0];
    const float inv1 = 1.f / lrow[1];
    __half* Og = g_att + (size_t)(b * SEQ + q0 + wq) * HID + h * HD;
    #pragma unroll
    for (int nt = 0; nt < 8; ++nt) {
        const int col = (nt << 3) + (lc << 1);
        *(uint32_t*)&Og[(size_t)lr * HID + col] =
            pack_h2(O[nt][0] * inv0, O[nt][1] * inv0);
        *(uint32_t*)&Og[(size_t)(lr + 8) * HID + col] =
            pack_h2(O[nt][2] * inv1, O[nt][3] * inv1);
    }
}

// ---------------- launch ----------------------------------------------------
extern "C" void kernel_launch(void* const* d_in, const int* in_sizes, int n_in,
                              void* d_out, int out_size)
{
    const float* hs = (const float*)d_in[0];
    const float* wq = (const float*)d_in[1];
    const float* bq = (const float*)d_in[2];
    const float* wk = (const float*)d_in[3];
    const float* bk = (const float*)d_in[4];
    const float* wv = (const float*)d_in[5];
    const float* bv = (const float*)d_in[6];
    const float* wo = (const float*)d_in[7];
    const float* bo = (const float*)d_in[8];
    float* out = (float*)d_out;

    __half *hp, *wqkvp, *wop, *ap;
    float *bqkvp;
    cudaGetSymbolAddress((void**)&hp, g_hs);
    cudaGetSymbolAddress((void**)&wqkvp, g_wqkv);
    cudaGetSymbolAddress((void**)&wop, g_wo);
    cudaGetSymbolAddress((void**)&ap, g_att);
    cudaGetSymbolAddress((void**)&bqkvp, g_bqkv);

    cudaFuncSetAttribute(gemm_h<0>, cudaFuncAttributeMaxDynamicSharedMemorySize, GEMM_SMEM);
    cudaFuncSetAttribute(gemm_h<3>, cudaFuncAttributeMaxDynamicSharedMemorySize, GEMM_SMEM);
    cudaFuncSetAttribute(attn_mma, cudaFuncAttributeMaxDynamicSharedMemorySize, ATT_SMEM_BYTES);

    conv_h<<<(MROWS * HID / 4) / 256, 256>>>((const float4*)hs, (__half2*)hp);
    conv_w4<<<(4 * HID * HID / 4) / 256, 256>>>(
        (const float4*)wq, (const float4*)wk, (const float4*)wv, (const float4*)wo,
        (__half2*)wqkvp, (__half2*)wop);
    conv_b<<<12, 256>>>(bq, bk, bv, bqkvp);

    dim3 qkvgrid(3 * HID / TBN, MROWS / TBM);  // (24, 32)
    gemm_h<3><<<qkvgrid, 256, GEMM_SMEM>>>(hp, wqkvp, bqkvp, nullptr);

    dim3 agrid(SEQ / QT, NH, BATCH);           // (32, 16, 2)
    attn_mma<<<agrid, ATHR, ATT_SMEM_BYTES>>>();

    dim3 ogrid(HID / TBN, MROWS / TBM);        // (8, 32)
    gemm_h<0><<<ogrid, 256, GEMM_SMEM>>>(ap, wop, bo, out);
}

// round 9
// speedup vs baseline: 7.8166x; 1.0499x over previous
#include <cuda_runtime.h>
#include <cuda_fp16.h>
#include <math.h>
#include <stdint.h>

// Problem constants
#define BATCH 2
#define SEQ   2048
#define HID   1024
#define NH    16
#define HD    64
#define MROWS (BATCH * SEQ)   // 4096

// Q pre-scale: HD^-0.5 * log2(e)  (softmax done in exp2 domain)
#define QSCALE (0.125f * 1.44269504088896f)

// ---------------- scratch (static device globals; no runtime alloc) ----------
__device__ __half g_q[MROWS * HID];      // pre-scaled by QSCALE
__device__ __half g_k[MROWS * HID];      // [seq][hid]
__device__ __half g_vt[MROWS * HID];     // [(b*NH+h)*HD+d][seq]
__device__ __half g_att[MROWS * HID];    // [seq][hid]
__device__ __half g_hs[MROWS * HID];
__device__ __half g_wqkv[3 * HID * HID]; // rows: [wq; wk; wv]
__device__ __half g_wo[HID * HID];
__device__ float  g_bqkv[3 * HID];

// ============================================================================
// helpers
// ============================================================================
__device__ __forceinline__ void cp16(uint32_t s, const void* g) {
    asm volatile("cp.async.cg.shared.global [%0], [%1], 16;" :: "r"(s), "l"(g));
}
#define CP_COMMIT() asm volatile("cp.async.commit_group;" ::: "memory")
template <int N>
__device__ __forceinline__ void cp_wait() {
    asm volatile("cp.async.wait_group %0;" :: "n"(N) : "memory");
}
__device__ __forceinline__ uint32_t smem_u32(const void* p) {
    uint32_t a;
    asm("{ .reg .u64 t; cvta.to.shared.u64 t, %1; cvt.u32.u64 %0, t; }"
        : "=r"(a) : "l"(p));
    return a;
}
__device__ __forceinline__ void mma_f16(
    float& c0, float& c1, float& c2, float& c3,
    uint32_t a0, uint32_t a1, uint32_t a2, uint32_t a3,
    uint32_t b0, uint32_t b1)
{
    asm volatile(
        "mma.sync.aligned.m16n8k16.row.col.f32.f16.f16.f32 "
        "{%0,%1,%2,%3}, {%4,%5,%6,%7}, {%8,%9}, {%0,%1,%2,%3};"
        : "+f"(c0), "+f"(c1), "+f"(c2), "+f"(c3)
        : "r"(a0), "r"(a1), "r"(a2), "r"(a3), "r"(b0), "r"(b1));
}
__device__ __forceinline__ void ldsm4(
    uint32_t& r0, uint32_t& r1, uint32_t& r2, uint32_t& r3, uint32_t a)
{
    asm volatile("ldmatrix.sync.aligned.m8n8.x4.shared.b16 {%0,%1,%2,%3}, [%4];"
                 : "=r"(r0), "=r"(r1), "=r"(r2), "=r"(r3) : "r"(a));
}
__device__ __forceinline__ uint32_t pack_h2(float a, float b) {
    __half2 h = __floats2half2_rn(a, b);
    return *(uint32_t*)&h;
}
__device__ __forceinline__ float ex2(float x) {
    float y;
    asm("ex2.approx.f32 %0, %1;" : "=f"(y) : "f"(x));
    return y;
}

// ============================================================================
// conversion kernels
// ============================================================================
__global__ void conv_h(const float4* __restrict__ in, __half2* __restrict__ out) {
    int i = blockIdx.x * blockDim.x + threadIdx.x;
    float4 v = in[i];
    out[2 * i]     = __floats2half2_rn(v.x, v.y);
    out[2 * i + 1] = __floats2half2_rn(v.z, v.w);
}

__global__ void conv_w4(const float4* __restrict__ wq, const float4* __restrict__ wk,
                        const float4* __restrict__ wv, const float4* __restrict__ wo,
                        __half2* __restrict__ wqkv, __half2* __restrict__ woh)
{
    int i = blockIdx.x * blockDim.x + threadIdx.x;
    int seg = i >> 18;
    int off = i & 0x3FFFF;
    const float4* src = seg == 0 ? wq : seg == 1 ? wk : seg == 2 ? wv : wo;
    float4 v = src[off];
    __half2 h0 = __floats2half2_rn(v.x, v.y);
    __half2 h1 = __floats2half2_rn(v.z, v.w);
    if (seg < 3) { wqkv[2 * i] = h0; wqkv[2 * i + 1] = h1; }
    else         { woh[2 * off] = h0; woh[2 * off + 1] = h1; }
}

__global__ void conv_b(const float* __restrict__ bq, const float* __restrict__ bk,
                       const float* __restrict__ bv, float* __restrict__ dst)
{
    int i = blockIdx.x * blockDim.x + threadIdx.x;
    const float* s = i < 1024 ? bq : i < 2048 ? bk : bv;
    dst[i] = s[i & 1023];
}

// ============================================================================
// fp16 GEMM: BK=64, 3-stage cp.async ring, ONE barrier per stage.
// MODE 0: out f32 = acc + bias (O-projection)
// MODE 3: fused QKV epilogue, segment by global column
// ============================================================================
#define TBM 128
#define TBN 128
#define TBK 64
#define KSTAGES (HID / TBK)     // 16
#define ASTR 72                 // halfs per smem row (144B)
#define MATH2 (128 * ASTR)      // 9216 halfs per matrix per stage
#define MATB2 (MATH2 * 2)       // 18432 bytes
#define GSTAGES 3
#define GEMM_SMEM (GSTAGES * 2 * MATB2)   // 110592

__device__ __forceinline__ void g_load_stage(
    uint32_t sbase, int slot,
    const __half* __restrict__ X, const __half* __restrict__ W,
    int m0, int n0, int k0, int t)
{
    uint32_t aB = sbase + (uint32_t)(slot * 2) * MATB2;
    uint32_t bB = aB + MATB2;
    #pragma unroll
    for (int i = 0; i < 4; ++i) {
        int cid = t + (i << 8);          // 0..1023
        int r = cid >> 3;                // row 0..127
        int c = cid & 7;                 // 16B chunk 0..7
        uint32_t off = (uint32_t)r * (ASTR * 2) + (uint32_t)c * 16;
        cp16(aB + off, X + (size_t)(m0 + r) * HID + k0 + (c << 3));
        cp16(bB + off, W + (size_t)(n0 + r) * HID + k0 + (c << 3));
    }
}

template <int MODE>
__global__ __launch_bounds__(256, 2) void gemm_h(
    const __half* __restrict__ X, const __half* __restrict__ W,
    const float* __restrict__ bias, void* __restrict__ outv)
{
    extern __shared__ __align__(16) __half hsm[];
    const uint32_t sbase = smem_u32(hsm);

    const int t    = threadIdx.x;
    const int wid  = t >> 5;
    const int lane = t & 31;
    const int wr   = (wid >> 2) << 6;
    const int wc   = (wid & 3) << 5;
    const int m0   = blockIdx.y * TBM;
    const int n0   = blockIdx.x * TBN;
    const int lr   = lane >> 2;
    const int lc   = lane & 3;

    const int i8 = lane & 7, j4 = lane >> 3;
    const uint32_t aRow = (uint32_t)(((j4 & 1) << 3) + i8);
    const uint32_t aKo  = (uint32_t)((j4 >> 1) << 3);
    const uint32_t bRow = (uint32_t)(((j4 >> 1) << 3) + i8);
    const uint32_t bKo  = (uint32_t)((j4 & 1) << 3);

    float acc[4][4][4] = {};

    g_load_stage(sbase, 0, X, W, m0, n0, 0, t);
    CP_COMMIT();
    g_load_stage(sbase, 1, X, W, m0, n0, TBK, t);
    CP_COMMIT();

    int slot = 0;
    for (int s = 0; s < KSTAGES; ++s) {
        if (s + 1 < KSTAGES) cp_wait<1>(); else cp_wait<0>();
        __syncthreads();

        if (s + 2 < KSTAGES) {
            int nslot = slot + 2; if (nslot >= GSTAGES) nslot -= GSTAGES;
            g_load_stage(sbase, nslot, X, W, m0, n0, (s + 2) * TBK, t);
            CP_COMMIT();
        }

        const uint32_t aB = sbase + (uint32_t)(slot * 2) * MATB2;
        const uint32_t bB = aB + MATB2;

        #pragma unroll
        for (int kk = 0; kk < 4; ++kk) {
            const uint32_t ko = (uint32_t)(kk << 4);
            uint32_t af[4][4];
            #pragma unroll
            for (int mi = 0; mi < 4; ++mi)
                ldsm4(af[mi][0], af[mi][1], af[mi][2], af[mi][3],
                      aB + (((uint32_t)(wr + (mi << 4)) + aRow) * ASTR + ko + aKo) * 2);
            uint32_t bf[4][2];
            #pragma unroll
            for (int p = 0; p < 2; ++p)
                ldsm4(bf[2 * p][0], bf[2 * p][1], bf[2 * p + 1][0], bf[2 * p + 1][1],
                      bB + (((uint32_t)(wc + (p << 4)) + bRow) * ASTR + ko + bKo) * 2);
            #pragma unroll
            for (int mi = 0; mi < 4; ++mi)
                #pragma unroll
                for (int ni = 0; ni < 4; ++ni)
                    mma_f16(acc[mi][ni][0], acc[mi][ni][1],
                            acc[mi][ni][2], acc[mi][ni][3],
                            af[mi][0], af[mi][1], af[mi][2], af[mi][3],
                            bf[ni][0], bf[ni][1]);
        }

        if (++slot >= GSTAGES) slot = 0;
    }

    const int seg = n0 >> 10;

    #pragma unroll
    for (int mi = 0; mi < 4; ++mi) {
        #pragma unroll
        for (int ni = 0; ni < 4; ++ni) {
            const int row = m0 + wr + (mi << 4) + lr;
            const int col = n0 + wc + (ni << 3) + (lc << 1);
            float2 b01 = *(const float2*)&bias[col];
            float v00 = acc[mi][ni][0] + b01.x;
            float v01 = acc[mi][ni][1] + b01.y;
            float v10 = acc[mi][ni][2] + b01.x;
            float v11 = acc[mi][ni][3] + b01.y;
            if (MODE == 0) {
                float* out = (float*)outv;
                *(float2*)&out[(size_t)row * HID + col] = make_float2(v00, v01);
                *(float2*)&out[(size_t)(row + 8) * HID + col] = make_float2(v10, v11);
            } else {
                const int c = col & 1023;
                if (seg == 0) {
                    *(uint32_t*)&g_q[(size_t)row * HID + c] =
                        pack_h2(QSCALE * v00, QSCALE * v01);
                    *(uint32_t*)&g_q[(size_t)(row + 8) * HID + c] =
                        pack_h2(QSCALE * v10, QSCALE * v11);
                } else if (seg == 1) {
                    *(uint32_t*)&g_k[(size_t)row * HID + c] = pack_h2(v00, v01);
                    *(uint32_t*)&g_k[(size_t)(row + 8) * HID + c] = pack_h2(v10, v11);
                } else {
                    const int b0i = row >> 11, s0 = row & 2047;
                    const int b1i = (row + 8) >> 11, s1 = (row + 8) & 2047;
                    const int h0 = c >> 6, d0 = c & 63;
                    const int h1 = (c + 1) >> 6, d1 = (c + 1) & 63;
                    g_vt[((size_t)(b0i * NH + h0) * HD + d0) * SEQ + s0] = __float2half(v00);
                    g_vt[((size_t)(b0i * NH + h1) * HD + d1) * SEQ + s0] = __float2half(v01);
                    g_vt[((size_t)(b1i * NH + h0) * HD + d0) * SEQ + s1] = __float2half(v10);
                    g_vt[((size_t)(b1i * NH + h1) * HD + d1) * SEQ + s1] = __float2half(v11);
                }
            }
        }
    }
}

// ============================================================================
// Flash attention: 3-stage KV ring + fragment software pipelining.
// ============================================================================
#define QT    64
#define ATHR  128
#define KT    64
#define NKT   (SEQ / KT)            // 32
#define HSTR  72                    // halfs per smem row (144B)
#define KSTG2 (KT * HSTR)           // 4608 halfs per stage
#define ASTAGES 3
#define VBASE2 (ASTAGES * KSTG2)    // 13824
#define PBASE2 (VBASE2 + ASTAGES * KSTG2)  // 27648
#define PWARP2 (16 * HSTR)          // 1152
#define ATT_SMEM_BYTES ((PBASE2 + 4 * PWARP2) * 2)  // 64512

__device__ __forceinline__ void a_load_kv(
    uint32_t sbase, int slot, int b, int h, int k0, int t)
{
    const uint32_t kB = sbase + (uint32_t)slot * (KSTG2 * 2);
    const uint32_t vB = sbase + (uint32_t)(VBASE2 + slot * KSTG2) * 2;
    #pragma unroll
    for (int i = 0; i < 4; ++i) {
        int cid = t + (i << 7);
        int r = cid >> 3;
        int c = cid & 7;
        cp16(kB + (uint32_t)r * (HSTR * 2) + (uint32_t)c * 16,
             g_k + (size_t)(b * SEQ + k0 + r) * HID + h * HD + (c << 3));
        cp16(vB + (uint32_t)r * (HSTR * 2) + (uint32_t)c * 16,
             g_vt + ((size_t)(b * NH + h) * HD + r) * SEQ + k0 + (c << 3));
    }
}

__global__ __launch_bounds__(ATHR, 3) void attn_mma()
{
    extern __shared__ __align__(16) __half hsm[];
    const uint32_t sbase = smem_u32(hsm);

    const int t    = threadIdx.x;
    const int wid  = t >> 5;
    const int lane = t & 31;
    const int lr   = lane >> 2;
    const int lc   = lane & 3;

    const int i8 = lane & 7, j4 = lane >> 3;
    const uint32_t aRow = (uint32_t)(((j4 & 1) << 3) + i8);
    const uint32_t aKo  = (uint32_t)((j4 >> 1) << 3);
    const uint32_t bRow = (uint32_t)(((j4 >> 1) << 3) + i8);
    const uint32_t bKo  = (uint32_t)((j4 & 1) << 3);

    const int b  = blockIdx.z;
    const int h  = blockIdx.y;
    const int q0 = blockIdx.x * QT;
    const int wq = wid << 4;

    uint32_t qf[4][4];
    {
        const __half* Qg = g_q + (size_t)(b * SEQ + q0 + wq) * HID + h * HD;
        #pragma unroll
        for (int ks = 0; ks < 4; ++ks) {
            const int ko = (ks << 4) + (lc << 1);
            qf[ks][0] = *(const uint32_t*)&Qg[(size_t)lr * HID + ko];
            qf[ks][1] = *(const uint32_t*)&Qg[(size_t)(lr + 8) * HID + ko];
            qf[ks][2] = *(const uint32_t*)&Qg[(size_t)lr * HID + ko + 8];
            qf[ks][3] = *(const uint32_t*)&Qg[(size_t)(lr + 8) * HID + ko + 8];
        }
    }

    float O[8][4] = {};
    float mrow[2] = {-1e30f, -1e30f};
    float lrow[2] = {0.f, 0.f};

    a_load_kv(sbase, 0, b, h, 0, t);
    CP_COMMIT();
    a_load_kv(sbase, 1, b, h, KT, t);
    CP_COMMIT();

    const uint32_t pB = sbase + (uint32_t)(PBASE2 + wid * PWARP2) * 2;
    __half* sPw = hsm + PBASE2 + wid * PWARP2;

    int slot = 0;
    for (int kt = 0; kt < NKT; ++kt) {
        if (kt + 1 < NKT) cp_wait<1>(); else cp_wait<0>();
        __syncthreads();

        if (kt + 2 < NKT) {
            int nslot = slot + 2; if (nslot >= ASTAGES) nslot -= ASTAGES;
            a_load_kv(sbase, nslot, b, h, (kt + 2) * KT, t);
            CP_COMMIT();
        }

        const uint32_t kB = sbase + (uint32_t)slot * (KSTG2 * 2);
        const uint32_t vB = sbase + (uint32_t)(VBASE2 + slot * KSTG2) * 2;

        // ---- S = Qs @ K^T, pipelined K-fragment loads ----
        float S[8][4] = {};
        {
            uint32_t kf0[4], kf1[4];
            ldsm4(kf0[0], kf0[1], kf0[2], kf0[3], kB + (bRow * HSTR + bKo) * 2);
            #pragma unroll
            for (int idx = 0; idx < 16; ++idx) {
                const int ks = idx >> 2, p = idx & 3;
                uint32_t* cur = (idx & 1) ? kf1 : kf0;
                uint32_t* nxt = (idx & 1) ? kf0 : kf1;
                if (idx < 15) {
                    const int nks = (idx + 1) >> 2, np = (idx + 1) & 3;
                    ldsm4(nxt[0], nxt[1], nxt[2], nxt[3],
                          kB + (((uint32_t)(np << 4) + bRow) * HSTR
                                + (uint32_t)(nks << 4) + bKo) * 2);
                }
                mma_f16(S[2*p][0], S[2*p][1], S[2*p][2], S[2*p][3],
                        qf[ks][0], qf[ks][1], qf[ks][2], qf[ks][3],
                        cur[0], cur[1]);
                mma_f16(S[2*p+1][0], S[2*p+1][1], S[2*p+1][2], S[2*p+1][3],
                        qf[ks][0], qf[ks][1], qf[ks][2], qf[ks][3],
                        cur[2], cur[3]);
            }
        }

        // ---- online softmax (exp2 domain) ----
        #pragma unroll
        for (int r = 0; r < 2; ++r) {
            const int e0 = r << 1, e1 = e0 + 1;
            float mt = -1e30f;
            #pragma unroll
            for (int nt = 0; nt < 8; ++nt)
                mt = fmaxf(mt, fmaxf(S[nt][e0], S[nt][e1]));
            mt = fmaxf(mt, __shfl_xor_sync(0xffffffffu, mt, 1));
            mt = fmaxf(mt, __shfl_xor_sync(0xffffffffu, mt, 2));
            float mnew = fmaxf(mrow[r], mt);
            float corr = ex2(mrow[r] - mnew);
            float rs = 0.f;
            #pragma unroll
            for (int nt = 0; nt < 8; ++nt) {
                float p0 = ex2(S[nt][e0] - mnew);
                float p1 = ex2(S[nt][e1] - mnew);
                S[nt][e0] = p0; S[nt][e1] = p1;
                rs += p0 + p1;
            }
            rs += __shfl_xor_sync(0xffffffffu, rs, 1);
            rs += __shfl_xor_sync(0xffffffffu, rs, 2);
            lrow[r] = lrow[r] * corr + rs;
            mrow[r] = mnew;
            #pragma unroll
            for (int nt = 0; nt < 8; ++nt) {
                O[nt][e0] *= corr;
                O[nt][e1] *= corr;
            }
        }

        // ---- P -> per-warp smem ----
        #pragma unroll
        for (int nt = 0; nt < 8; ++nt) {
            const int col = (nt << 3) + (lc << 1);
            *(uint32_t*)&sPw[lr * HSTR + col]       = pack_h2(S[nt][0], S[nt][1]);
            *(uint32_t*)&sPw[(lr + 8) * HSTR + col] = pack_h2(S[nt][2], S[nt][3]);
        }
        __syncwarp();

        // ---- O += P @ V, pipelined P/V fragment loads ----
        {
            uint32_t af0[4], af1[4], vf0[4], vf1[4];
            ldsm4(af0[0], af0[1], af0[2], af0[3], pB + (aRow * HSTR + aKo) * 2);
            ldsm4(vf0[0], vf0[1], vf0[2], vf0[3], vB + (bRow * HSTR + bKo) * 2);
            #pragma unroll
            for (int idx = 0; idx < 16; ++idx) {
                const int ks = idx >> 2, p = idx & 3;
                uint32_t* cura = (ks & 1) ? af1 : af0;
                uint32_t* nxta = (ks & 1) ? af0 : af1;
                uint32_t* curv = (idx & 1) ? vf1 : vf0;
                uint32_t* nxtv = (idx & 1) ? vf0 : vf1;
                if (p == 0 && ks < 3)
                    ldsm4(nxta[0], nxta[1], nxta[2], nxta[3],
                          pB + (aRow * HSTR + (uint32_t)((ks + 1) << 4) + aKo) * 2);
                if (idx < 15) {
                    const int nks = (idx + 1) >> 2, np = (idx + 1) & 3;
                    ldsm4(nxtv[0], nxtv[1], nxtv[2], nxtv[3],
                          vB + (((uint32_t)(np << 4) + bRow) * HSTR
                                + (uint32_t)(nks << 4) + bKo) * 2);
                }
                mma_f16(O[2*p][0], O[2*p][1], O[2*p][2], O[2*p][3],
                        cura[0], cura[1], cura[2], cura[3], curv[0], curv[1]);
                mma_f16(O[2*p+1][0], O[2*p+1][1], O[2*p+1][2], O[2*p+1][3],
                        cura[0], cura[1], cura[2], cura[3], curv[2], curv[3]);
            }
        }

        if (++slot >= ASTAGES) slot = 0;
    }

    // ---- normalize + store half ----
    const float inv0 = 1.f / lrow[0];
    const float inv1 = 1.f / lrow[1];
    __half* Og = g_att + (size_t)(b * SEQ + q0 + wq) * HID + h * HD;
    #pragma unroll
    for (int nt = 0; nt < 8; ++nt) {
        const int col = (nt << 3) + (lc << 1);
        *(uint32_t*)&Og[(size_t)lr * HID + col] =
            pack_h2(O[nt][0] * inv0, O[nt][1] * inv0);
        *(uint32_t*)&Og[(size_t)(lr + 8) * HID + col] =
            pack_h2(O[nt][2] * inv1, O[nt][3] * inv1);
    }
}

// ---------------- launch ----------------------------------------------------
extern "C" void kernel_launch(void* const* d_in, const int* in_sizes, int n_in,
                              void* d_out, int out_size)
{
    const float* hs = (const float*)d_in[0];
    const float* wq = (const float*)d_in[1];
    const float* bq = (const float*)d_in[2];
    const float* wk = (const float*)d_in[3];
    const float* bk = (const float*)d_in[4];
    const float* wv = (const float*)d_in[5];
    const float* bv = (const float*)d_in[6];
    const float* wo = (const float*)d_in[7];
    const float* bo = (const float*)d_in[8];
    float* out = (float*)d_out;

    __half *hp, *wqkvp, *wop, *ap;
    float *bqkvp;
    cudaGetSymbolAddress((void**)&hp, g_hs);
    cudaGetSymbolAddress((void**)&wqkvp, g_wqkv);
    cudaGetSymbolAddress((void**)&wop, g_wo);
    cudaGetSymbolAddress((void**)&ap, g_att);
    cudaGetSymbolAddress((void**)&bqkvp, g_bqkv);

    cudaFuncSetAttribute(gemm_h<0>, cudaFuncAttributeMaxDynamicSharedMemorySize, GEMM_SMEM);
    cudaFuncSetAttribute(gemm_h<3>, cudaFuncAttributeMaxDynamicSharedMemorySize, GEMM_SMEM);
    cudaFuncSetAttribute(attn_mma, cudaFuncAttributeMaxDynamicSharedMemorySize, ATT_SMEM_BYTES);

    conv_h<<<(MROWS * HID / 4) / 256, 256>>>((const float4*)hs, (__half2*)hp);
    conv_w4<<<(4 * HID * HID / 4) / 256, 256>>>(
        (const float4*)wq, (const float4*)wk, (const float4*)wv, (const float4*)wo,
        (__half2*)wqkvp, (__half2*)wop);
    conv_b<<<12, 256>>>(bq, bk, bv, bqkvp);

    dim3 qkvgrid(3 * HID / TBN, MROWS / TBM);  // (24, 32)
    gemm_h<3><<<qkvgrid, 256, GEMM_SMEM>>>(hp, wqkvp, bqkvp, nullptr);

    dim3 agrid(SEQ / QT, NH, BATCH);           // (32, 16, 2)
    attn_mma<<<agrid, ATHR, ATT_SMEM_BYTES>>>();

    dim3 ogrid(HID / TBN, MROWS / TBM);        // (8, 32)
    gemm_h<0><<<ogrid, 256, GEMM_SMEM>>>(ap, wop, bo, out);
}